// round 2
// baseline (speedup 1.0000x reference)
#include <cuda_runtime.h>
#include <math.h>
#include <stdint.h>

#define PI_D 3.14159265358979323846

// Problem constants
// B_IN=64, B_OUT=20, B_INV=20, BATCH=16, F_IN=16, F_OUT=32, N_GRID=24
// 2*B_IN = 128 (input grid), 2*B_INV = 40 (output grid)
// half-pair count: sum_l (l+1)(2l+1) = 5530

__constant__ int c_hoff[20] = {0,1,7,22,50,95,161,252,372,525,715,946,1222,1547,1925,2360,2856,3417,4047,4750};

__device__ float  g_ws2[128*400];      // [beta_b][lm]   l-block layout lm = l*l + (m+l)
__device__ float2 g_cFk[24*400];       // conj(F_k) [p][lm]
__device__ float  g_dh[40*5530];       // (2l+1)*d^l_{m,n}(beta_b), m>=0 half, [b][hpair]
__device__ unsigned int g_pinfo[5530]; // (l<<12)|(m<<6)|ni
__device__ float2 g_Xf[20*128*256];    // [m][b][zi]  DFT bins m=0..19
__device__ float2 g_xl[16*400*16];     // [z][lm][i]
__device__ float2 g_cy[32*400*16];     // [o][lm][i]  = conj(y)*SCALING
__device__ float2 g_zl[512*5530];      // [zo][hpair]

// ---------------- Wigner-d (double, factorial-product form) ----------------
__device__ __forceinline__ double wig(int l, int m, int n,
                                      const double* f, const double* rf,
                                      const double* cbp, const double* sbp) {
    double pref = sqrt(f[l+m]*f[l-m]*f[l+n]*f[l-n]);
    int s0 = (n-m) > 0 ? (n-m) : 0;
    int s1 = (l+n) < (l-m) ? (l+n) : (l-m);
    double v = 0.0;
    for (int s = s0; s <= s1; s++) {
        double t = pref * rf[l+n-s] * rf[s] * rf[m-n+s] * rf[l-m-s]
                 * cbp[2*l+n-m-2*s] * sbp[m-n+2*s];
        v += ((m-n+s) & 1) ? -t : t;
    }
    return v;
}

__device__ __forceinline__ void prep_tables(double beta, double* f, double* rf,
                                            double* cbp, double* sbp) {
    f[0] = 1.0;
    for (int k = 1; k < 41; k++) f[k] = f[k-1] * (double)k;
    for (int k = 0; k < 41; k++) rf[k] = 1.0 / f[k];
    double cb = cos(beta*0.5), sb = sin(beta*0.5);
    cbp[0] = 1.0; sbp[0] = 1.0;
    for (int k = 1; k < 41; k++) { cbp[k] = cbp[k-1]*cb; sbp[k] = sbp[k-1]*sb; }
}

__device__ __forceinline__ void lm_split(int lm, int& l, int& m) {
    l = (int)sqrtf((float)lm);
    while ((l+1)*(l+1) <= lm) l++;
    while (l*l > lm) l--;
    m = lm - l*l - l;
}

// ---------------- init kernels ----------------
__global__ void k_init_ws2() {
    __shared__ double sf[41], srf[41], scb[41], ssb[41];
    __shared__ double sw;
    int b = blockIdx.x;
    double beta = PI_D * (2.0*b + 1.0) / 256.0;
    if (threadIdx.x == 0) {
        prep_tables(beta, sf, srf, scb, ssb);
        double acc = 0.0;
        for (int k = 0; k < 64; k++) acc += sin((2.0*k+1.0)*beta) / (2.0*k+1.0);
        sw = (2.0/64.0) * sin(beta) * acc;
    }
    __syncthreads();
    for (int lm = threadIdx.x; lm < 400; lm += blockDim.x) {
        int l, m; lm_split(lm, l, m);
        g_ws2[b*400 + lm] = (float)(wig(l, m, 0, sf, srf, scb, ssb) * sw);
    }
}

__global__ void k_init_cfk() {
    __shared__ double sf[41], srf[41], scb[41], ssb[41];
    int p = blockIdx.x;
    double beta  = ((p >> 3) + 1) * PI_D / 24.0;
    double alpha = (p & 7) * (PI_D / 4.0);
    if (threadIdx.x == 0) prep_tables(beta, sf, srf, scb, ssb);
    __syncthreads();
    for (int lm = threadIdx.x; lm < 400; lm += blockDim.x) {
        int l, m; lm_split(lm, l, m);
        double d = wig(l, m, 0, sf, srf, scb, ssb);
        double ph = (double)m * alpha;   // conj(e^{-i m a}) = e^{+i m a}
        g_cFk[p*400 + lm] = make_float2((float)(d*cos(ph)), (float)(d*sin(ph)));
    }
}

__global__ void k_init_dh() {
    __shared__ double sf[41], srf[41], scb[41], ssb[41];
    int b = blockIdx.x;   // 40
    int l = blockIdx.y;   // 20
    double beta = PI_D * (2.0*b + 1.0) / 80.0;
    if (threadIdx.x == 0) prep_tables(beta, sf, srf, scb, ssb);
    __syncthreads();
    int w = 2*l + 1;
    int cnt = (l+1) * w;
    for (int e = threadIdx.x; e < cnt; e += blockDim.x) {
        int m = e / w, ni = e % w;
        g_dh[b*5530 + c_hoff[l] + e] = (float)((double)w * wig(l, m, ni - l, sf, srf, scb, ssb));
    }
}

__global__ void k_init_pinfo() {
    int p = blockIdx.x * blockDim.x + threadIdx.x;
    if (p >= 5530) return;
    int l = 0, acc = 0;
    for (; l < 20; l++) {
        int sz = (l+1)*(2*l+1);
        if (p < acc + sz) break;
        acc += sz;
    }
    int r = p - acc;
    int w = 2*l + 1;
    g_pinfo[p] = (unsigned)((l << 12) | ((r / w) << 6) | (r % w));
}

// ---------------- K1: truncated real DFT over alpha (m = 0..19) ----------------
__global__ void k_dft(const float* __restrict__ x) {
    __shared__ float xs[8][128];
    int bg = blockIdx.x;     // 16 groups of 8 betas
    int zi = blockIdx.y;     // 256
    const float* xp = x + (zi * 128 + bg * 8) * 128;
    for (int idx = threadIdx.x; idx < 1024; idx += blockDim.x)
        xs[idx >> 7][idx & 127] = xp[idx];
    __syncthreads();
    int b8 = threadIdx.x >> 5, m = threadIdx.x & 31;
    if (m < 20) {
        float ss, cc;
        sincospif(-(float)m / 64.0f, &ss, &cc);   // step e^{-2 pi i m /128}
        float cr = 1.0f, ci = 0.0f, ar = 0.0f, ai = 0.0f;
        for (int a = 0; a < 128; a++) {
            float xv = xs[b8][a];
            ar += xv * cr; ai += xv * ci;
            float nr = cr*cc - ci*ss;
            ci = cr*ss + ci*cc;
            cr = nr;
        }
        int b = bg * 8 + b8;
        g_Xf[(m * 128 + b) * 256 + zi] = make_float2(ar, ai);
    }
}

// ---------------- K2: S2 analysis  xl[z][lm][i] ----------------
__global__ void k_xl() {
    int lm = blockIdx.x * 16 + (threadIdx.x >> 4);
    int z  = blockIdx.y;
    int i  = threadIdx.x & 15;
    if (lm >= 400) return;
    int l, m; lm_split(lm, l, m);
    int ma = m < 0 ? -m : m;
    const float*  wp = g_ws2 + lm;                       // stride 400
    const float2* Xp = g_Xf + (size_t)ma * 128 * 256 + (z * 16 + i);
    float ar = 0.0f, ai = 0.0f;
    for (int b = 0; b < 128; b++) {
        float w = wp[b * 400];
        float2 xv = Xp[b * 256];
        ar += w * xv.x; ai += w * xv.y;
    }
    if (m < 0) ai = -ai;                                 // conj for negative freq
    g_xl[((size_t)z * 400 + lm) * 16 + i] = make_float2(ar, ai);
}

// ---------------- K3: cy = SCALING * conj(y) ----------------
__global__ void k_cy(const float* __restrict__ kern) {
    __shared__ float2 sF[24];
    int lm = blockIdx.x;
    if (threadIdx.x < 24) sF[threadIdx.x] = g_cFk[threadIdx.x * 400 + lm];
    __syncthreads();
    int i = threadIdx.x >> 5, o = threadIdx.x & 31;
    const float* kp = kern + (i * 32 + o) * 24;
    float ar = 0.0f, ai = 0.0f;
    for (int p = 0; p < 24; p++) {
        float k = kp[p];
        ar += k * sF[p].x; ai += k * sF[p].y;
    }
    const float S = 0.00816496580927726f;  // 1/sqrt(15000)
    g_cy[((size_t)o * 400 + lm) * 16 + i] = make_float2(ar * S, ai * S);
}

// ---------------- K4: zl[zo][hpair] = sum_i xl[l,m] * cy[l,n] (m>=0 half) ----------------
__global__ void k_zl() {
    extern __shared__ float2 sm4[];
    float2* xs = sm4;          // [lm][i]  400*16
    float2* cs = sm4 + 6400;   // [lm][i]  padded stride 17 -> 400*17
    int o = blockIdx.x, z = blockIdx.y;
    for (int idx = threadIdx.x; idx < 6400; idx += blockDim.x) {
        xs[idx] = g_xl[(size_t)z * 6400 + idx];
        int lm = idx >> 4, i = idx & 15;
        cs[lm * 17 + i] = g_cy[(size_t)o * 6400 + idx];
    }
    __syncthreads();
    float2* out = g_zl + (size_t)(z * 32 + o) * 5530;
    for (int p = threadIdx.x; p < 5530; p += blockDim.x) {
        unsigned info = g_pinfo[p];
        int l = info >> 12, m = (info >> 6) & 63, ni = info & 63;
        const float2* A  = xs + (l*l + l + m) * 16;
        const float2* Bc = cs + (l*l + ni) * 17;
        float ar = 0.0f, ai = 0.0f;
        #pragma unroll
        for (int i = 0; i < 16; i++) {
            float2 a = A[i], c = Bc[i];
            ar += a.x*c.x - a.y*c.y;
            ai += a.x*c.y + a.y*c.x;
        }
        out[p] = make_float2(ar, ai);
    }
}

// ---------------- K5: fused G-build + inverse 2D synthesis ----------------
__global__ void k_out(const float* __restrict__ bias, float* __restrict__ out) {
    extern __shared__ float smemraw[];
    float2* zs  = (float2*)smemraw;   // 5530
    float2* G   = zs + 5530;          // 20 x 40 (m=0..19, nj=0..38)
    float2* H   = G + 800;            // 20 x 40 (m=0..19, g=0..39)
    float*  twc = (float*)(H + 800);  // 40
    float*  tws = twc + 40;           // 40
    int o = blockIdx.x, z = blockIdx.y;
    int zo = z * 32 + o;
    int t = threadIdx.x;
    if (t < 40) {
        float s, c;
        sincospif((float)t / 20.0f, &s, &c);   // e^{2 pi i t/40}
        twc[t] = c; tws[t] = s;
    }
    const float2* zp = g_zl + (size_t)zo * 5530;
    for (int idx = t; idx < 5530; idx += blockDim.x) zs[idx] = zp[idx];
    float bv = bias[o];
    float* op = out + (size_t)zo * 64000;
    __syncthreads();

    for (int b = 0; b < 40; b++) {
        const float* dB = g_dh + b * 5530;
        // --- G[m][n] = sum_l zl * d   (m >= 0 half only; Hermitian handles rest)
        for (int e = t; e < 780; e += blockDim.x) {
            int m = e / 39, nj = e % 39, n = nj - 19;
            int an = n < 0 ? -n : n;
            int lmin = m > an ? m : an;
            float gr = 0.0f, gi = 0.0f;
            for (int l = lmin; l < 20; l++) {
                int idx = c_hoff[l] + m * (2*l + 1) + (n + l);
                float d = dB[idx];
                float2 zv = zs[idx];
                gr += zv.x * d; gi += zv.y * d;
            }
            G[m * 40 + nj] = make_float2(gr, gi);
        }
        __syncthreads();
        // --- stage 1: H[m][g] = sum_n G[m][n] e^{2 pi i n g/40}
        for (int e = t; e < 800; e += blockDim.x) {
            int m = e / 40, g = e % 40;
            int k = (40 - (19 * g) % 40) % 40;   // start at n=-19
            const float2* Gp = G + m * 40;
            float hr = 0.0f, hi = 0.0f;
            #pragma unroll
            for (int nj = 0; nj < 39; nj++) {
                float c = twc[k], s = tws[k];
                float2 gv = Gp[nj];
                hr += gv.x * c - gv.y * s;
                hi += gv.x * s + gv.y * c;
                k += g; if (k >= 40) k -= 40;
            }
            H[e] = make_float2(hr, hi);
        }
        __syncthreads();
        // --- stage 2: f[a][g] = Re H[0][g] + 2 sum_{m>=1} Re(H[m][g] e^{2 pi i m a/40})
        for (int e = t; e < 1600; e += blockDim.x) {
            int a = e / 40, g = e % 40;
            float acc = H[g].x;
            int k = a;
            #pragma unroll
            for (int m = 1; m < 20; m++) {
                float2 hv = H[m * 40 + g];
                acc += 2.0f * (hv.x * twc[k] - hv.y * tws[k]);
                k += a; if (k >= 40) k -= 40;
            }
            op[(b * 40 + a) * 40 + g] = acc + bv;
        }
        __syncthreads();
    }
}

// ---------------- launch ----------------
extern "C" void kernel_launch(void* const* d_in, const int* in_sizes, int n_in,
                              void* d_out, int out_size) {
    const float* x    = (const float*)d_in[0];
    const float* kern = (const float*)d_in[1];
    const float* bias = (const float*)d_in[2];
    float* out = (float*)d_out;

    cudaFuncSetAttribute(k_zl,  cudaFuncAttributeMaxDynamicSharedMemorySize, 105600);
    cudaFuncSetAttribute(k_out, cudaFuncAttributeMaxDynamicSharedMemorySize, 57360);

    // constants (recomputed every launch: deterministic, no caching)
    k_init_ws2  <<<128, 256>>>();
    k_init_cfk  <<<24, 256>>>();
    k_init_dh   <<<dim3(40, 20), 256>>>();
    k_init_pinfo<<<22, 256>>>();

    // main pipeline
    k_dft<<<dim3(16, 256), 256>>>(x);
    k_xl <<<dim3(25, 16), 256>>>();
    k_cy <<<400, 512>>>(kern);
    k_zl <<<dim3(32, 16), 256, 105600>>>();
    k_out<<<dim3(32, 16), 512, 57360>>>(bias, out);
}

// round 5
// speedup vs baseline: 1.5704x; 1.5704x over previous
#include <cuda_runtime.h>
#include <math.h>
#include <stdint.h>

#define PI_D 3.14159265358979323846

// B_IN=64, B_OUT=20, B_INV=20, BATCH=16, F_IN=16, F_OUT=32, N_GRID=24
// half-pair count: sum_l (l+1)(2l+1) = 5530

__constant__ int c_hoff[20] = {0,1,7,22,50,95,161,252,372,525,715,946,1222,1547,1925,2360,2856,3417,4047,4750};

__device__ float  g_ws2[128*400];      // [beta_b][lm]  lm = l*l + (m+l)
__device__ float2 g_cFk[24*400];       // conj(F_k) [p][lm]
__device__ float  g_dh[40*5530];       // (2l+1)*d^l_{m,n}(beta_b), m>=0 half, [b][hpair]
__device__ unsigned int g_pinfo[5530]; // (l<<12)|(m<<6)|ni
__device__ float2 g_Xf[20*128*256];    // [m][b][zi]
__device__ float2 g_xl[16*400*16];     // [z][lm][i]
__device__ float2 g_cy[32*400*16];     // [o][lm][i]
__device__ float2 g_zl[512*5530];      // [zo][hpair]

// ---------- fp32 Wigner-d: log-space seed + upward 3-term recurrence ----------
__device__ __forceinline__ float wseed(int m, int n, float lcb, float lsb, const float* lf) {
    int am = m < 0 ? -m : m, an = n < 0 ? -n : n;
    int l = am > an ? am : an;
    float v;
    if (am >= an) {
        float lc = 0.5f*(lf[2*l] - lf[l+n] - lf[l-n]);
        if (m >= 0) { v = expf(lc + (l+n)*lcb + (l-n)*lsb); if ((l-n)&1) v = -v; }
        else        { v = expf(lc + (l-n)*lcb + (l+n)*lsb); }
    } else {
        float lc = 0.5f*(lf[2*l] - lf[l+m] - lf[l-m]);
        if (n >= 0) { v = expf(lc + (l+m)*lcb + (l-m)*lsb); }
        else        { v = expf(lc + (l-m)*lcb + (l+m)*lsb); if ((l+m)&1) v = -v; }
    }
    return v;
}

// ---------- combined init kernel ----------
// blocks 0..127: w_s2 (128 input betas); 128..151: cFk (24 grid pts);
// 152..191: dh (40 output betas); 192: pinfo
__global__ void k_init() {
    __shared__ float lf[41];
    __shared__ double sterm[64];
    __shared__ double swq;
    int t = threadIdx.x;
    if (t <= 40) lf[t] = lgammaf((float)(t + 1));
    int blk = blockIdx.x;

    if (blk < 128) {
        int b = blk;
        double beta = PI_D * (2.0*b + 1.0) / 256.0;
        if (t < 64) sterm[t] = sin((2.0*t + 1.0) * beta) / (2.0*t + 1.0);
        __syncthreads();
        if (t == 0) {
            double acc = 0.0;
            for (int k = 0; k < 64; k++) acc += sterm[k];
            swq = (2.0/64.0) * sin(beta) * acc;
        }
        __syncthreads();
        float w = (float)swq;
        float cb = (float)cos(beta*0.5), sb = (float)sin(beta*0.5);
        float cosb = (float)cos(beta);
        float lcb = logf(cb), lsb = logf(sb);
        if (t < 39) {
            int m = t - 19;
            int am = m < 0 ? -m : m;
            int l0 = am;
            float d1 = wseed(m, 0, lcb, lsb, lf), d2 = 0.0f;
            g_ws2[b*400 + l0*l0 + l0 + m] = d1 * w;
            int jstart = l0 + 1;
            if (l0 == 0) {              // m=0 chain: first recurrence step is 0/0; seed analytically
                d2 = d1; d1 = cosb;     // d^0_{00}=1, d^1_{00}=cos(beta)
                g_ws2[b*400 + 2] = d1 * w;   // l=1,m=0 -> idx 1*1+1+0
                jstart = 2;
            }
            for (int j = jstart; j <= 19; j++) {
                float wj  = sqrtf((float)((j*j - m*m) * (j*j)));
                float wj1 = sqrtf((float)(((j-1)*(j-1) - m*m) * ((j-1)*(j-1))));
                float d = ((2*j-1)*((float)(j*(j-1))*cosb) * d1 - (float)j*wj1*d2) / ((float)(j-1)*wj);
                g_ws2[b*400 + j*j + j + m] = d * w;
                d2 = d1; d1 = d;
            }
        }
    } else if (blk < 152) {
        int p = blk - 128;
        __syncthreads();
        double beta  = ((p >> 3) + 1) * PI_D / 24.0;
        float cb = (float)cos(beta*0.5), sb = (float)sin(beta*0.5);
        float cosb = (float)cos(beta);
        float lcb = logf(cb), lsb = logf(sb);
        if (t < 39) {
            int m = t - 19;
            int am = m < 0 ? -m : m;
            int l0 = am;
            float cph, sph;
            sincospif((float)(m * (p & 7)) * 0.25f, &sph, &cph);   // e^{+i m alpha}
            float d1 = wseed(m, 0, lcb, lsb, lf), d2 = 0.0f;
            g_cFk[p*400 + l0*l0 + l0 + m] = make_float2(d1*cph, d1*sph);
            int jstart = l0 + 1;
            if (l0 == 0) {
                d2 = d1; d1 = cosb;
                g_cFk[p*400 + 2] = make_float2(d1*cph, d1*sph);
                jstart = 2;
            }
            for (int j = jstart; j <= 19; j++) {
                float wj  = sqrtf((float)((j*j - m*m) * (j*j)));
                float wj1 = sqrtf((float)(((j-1)*(j-1) - m*m) * ((j-1)*(j-1))));
                float d = ((2*j-1)*((float)(j*(j-1))*cosb) * d1 - (float)j*wj1*d2) / ((float)(j-1)*wj);
                g_cFk[p*400 + j*j + j + m] = make_float2(d*cph, d*sph);
                d2 = d1; d1 = d;
            }
        }
    } else if (blk < 192) {
        int b = blk - 152;
        __syncthreads();
        double beta = PI_D * (2.0*b + 1.0) / 80.0;
        float cb = (float)cos(beta*0.5), sb = (float)sin(beta*0.5);
        float cosb = (float)cos(beta);
        float lcb = logf(cb), lsb = logf(sb);
        for (int p = t; p < 780; p += blockDim.x) {
            int m = p / 39, nj = p % 39, n = nj - 19;
            int an = n < 0 ? -n : n;
            int l0 = m > an ? m : an;
            float d1 = wseed(m, n, lcb, lsb, lf), d2 = 0.0f;
            g_dh[b*5530 + c_hoff[l0] + m*(2*l0+1) + n + l0] = (float)(2*l0+1) * d1;
            int jstart = l0 + 1;
            if (l0 == 0) {              // (m,n)=(0,0) chain
                d2 = d1; d1 = cosb;
                g_dh[b*5530 + c_hoff[1] + 0*3 + 0 + 1] = 3.0f * d1;   // l=1
                jstart = 2;
            }
            float mn = (float)(m * n);
            for (int j = jstart; j <= 19; j++) {
                float wj  = sqrtf((float)((j*j - m*m) * (j*j - n*n)));
                float wj1 = sqrtf((float)(((j-1)*(j-1) - m*m) * ((j-1)*(j-1) - n*n)));
                float d = ((2*j-1)*((float)(j*(j-1))*cosb - mn) * d1 - (float)j*wj1*d2) / ((float)(j-1)*wj);
                g_dh[b*5530 + c_hoff[j] + m*(2*j+1) + n + j] = (float)(2*j+1) * d;
                d2 = d1; d1 = d;
            }
        }
    } else {
        __syncthreads();
        for (int p = t; p < 5530; p += blockDim.x) {
            int l = 0, acc = 0;
            for (; l < 20; l++) {
                int sz = (l+1)*(2*l+1);
                if (p < acc + sz) break;
                acc += sz;
            }
            int r = p - acc, w = 2*l + 1;
            g_pinfo[p] = (unsigned)((l << 12) | ((r / w) << 6) | (r % w));
        }
    }
}

// ---------- K1: truncated real DFT over alpha (m = 0..19) ----------
__global__ void k_dft(const float* __restrict__ x) {
    __shared__ float xs[8][128];
    int bg = blockIdx.x, zi = blockIdx.y;
    const float* xp = x + (zi * 128 + bg * 8) * 128;
    for (int idx = threadIdx.x; idx < 1024; idx += blockDim.x)
        xs[idx >> 7][idx & 127] = xp[idx];
    __syncthreads();
    int b8 = threadIdx.x >> 5, m = threadIdx.x & 31;
    if (m < 20) {
        float ss, cc;
        sincospif(-(float)m / 64.0f, &ss, &cc);
        float cr = 1.0f, ci = 0.0f, ar = 0.0f, ai = 0.0f;
        for (int a = 0; a < 128; a++) {
            float xv = xs[b8][a];
            ar += xv * cr; ai += xv * ci;
            float nr = cr*cc - ci*ss;
            ci = cr*ss + ci*cc;
            cr = nr;
        }
        int b = bg * 8 + b8;
        g_Xf[(m * 128 + b) * 256 + zi] = make_float2(ar, ai);
    }
}

// ---------- K2: S2 analysis, tiled by (|m|, z) ----------
__global__ void k_xl2() {
    __shared__ float2 Xs[128*16];
    __shared__ float wsp[128*20];
    __shared__ float wsm[128*20];
    int ma = blockIdx.x, z = blockIdx.y;
    int nl = 20 - ma;
    int t = threadIdx.x;
    for (int idx = t; idx < 2048; idx += 256) {
        int b = idx >> 4, i = idx & 15;
        Xs[idx] = g_Xf[(ma*128 + b)*256 + z*16 + i];
    }
    for (int idx = t; idx < 128*nl; idx += 256) {
        int b = idx / nl, li = idx % nl;
        int l = ma + li;
        wsp[idx] = g_ws2[b*400 + l*l + l + ma];
        if (ma > 0) wsm[idx] = g_ws2[b*400 + l*l + l - ma];
    }
    __syncthreads();
    for (int item = t; item < nl*16; item += 256) {
        int li = item >> 4, i = item & 15;
        int l = ma + li;
        float pr = 0.f, pi = 0.f, mr = 0.f, mi = 0.f;
        for (int b = 0; b < 128; b++) {
            float2 xv = Xs[b*16 + i];
            float wp = wsp[b*nl + li];
            pr += wp * xv.x; pi += wp * xv.y;
            if (ma > 0) {
                float wm = wsm[b*nl + li];
                mr += wm * xv.x; mi -= wm * xv.y;
            }
        }
        g_xl[((size_t)z*400 + l*l + l + ma)*16 + i] = make_float2(pr, pi);
        if (ma > 0)
            g_xl[((size_t)z*400 + l*l + l - ma)*16 + i] = make_float2(mr, mi);
    }
}

// ---------- K3: cy = SCALING * conj(y) ----------
__global__ void k_cy(const float* __restrict__ kern) {
    __shared__ float2 sF[24];
    int lm = blockIdx.x;
    if (threadIdx.x < 24) sF[threadIdx.x] = g_cFk[threadIdx.x * 400 + lm];
    __syncthreads();
    int i = threadIdx.x >> 5, o = threadIdx.x & 31;
    const float* kp = kern + (i * 32 + o) * 24;
    float ar = 0.0f, ai = 0.0f;
    for (int p = 0; p < 24; p++) {
        float k = kp[p];
        ar += k * sF[p].x; ai += k * sF[p].y;
    }
    const float S = 0.00816496580927726f;  // 1/sqrt(15000)
    g_cy[((size_t)o * 400 + lm) * 16 + i] = make_float2(ar * S, ai * S);
}

// ---------- K4: zl[zo][hpair] ----------
__global__ void k_zl() {
    extern __shared__ float2 sm4[];
    float2* xs = sm4;
    float2* cs = sm4 + 6400;
    int o = blockIdx.x, z = blockIdx.y;
    for (int idx = threadIdx.x; idx < 6400; idx += blockDim.x) {
        xs[idx] = g_xl[(size_t)z * 6400 + idx];
        int lm = idx >> 4, i = idx & 15;
        cs[lm * 17 + i] = g_cy[(size_t)o * 6400 + idx];
    }
    __syncthreads();
    float2* outp = g_zl + (size_t)(z * 32 + o) * 5530;
    for (int p = threadIdx.x; p < 5530; p += blockDim.x) {
        unsigned info = g_pinfo[p];
        int l = info >> 12, m = (info >> 6) & 63, ni = info & 63;
        const float2* A  = xs + (l*l + l + m) * 16;
        const float2* Bc = cs + (l*l + ni) * 17;
        float ar = 0.0f, ai = 0.0f;
        #pragma unroll
        for (int i = 0; i < 16; i++) {
            float2 a = A[i], c = Bc[i];
            ar += a.x*c.x - a.y*c.y;
            ai += a.x*c.y + a.y*c.x;
        }
        outp[p] = make_float2(ar, ai);
    }
}

// ---------- K5: fused G-build + factorized (8x5) inverse 2D synthesis ----------
__global__ void k_out(const float* __restrict__ bias, float* __restrict__ out) {
    extern __shared__ float smemraw[];
    float2* zs  = (float2*)smemraw;          // 5530
    float2* G   = zs + 5530;                 // [m 20][j 40]
    float2* Y   = G + 800;                   // [m 20][r 5][u 8]
    float2* H   = Y + 800;                   // [m 20][g 40]  (H' with m=0 halved)
    float2* Z   = H + 800;                   // [r2 5][u 8][g 40]
    float2* tw  = Z + 1600;                  // 40: e^{2pi i k/40}
    float2* w8s = tw + 40;                   // 8:  e^{2pi i k/8}
    int o = blockIdx.x, z = blockIdx.y, bh = blockIdx.z;
    int zo = z * 32 + o;
    int t = threadIdx.x;
    if (t < 40) {
        float s, c;
        sincospif((float)t / 20.0f, &s, &c);
        tw[t] = make_float2(c, s);
    }
    if (t >= 64 && t < 72) {
        float s, c;
        sincospif((float)(t - 64) * 0.25f, &s, &c);
        w8s[t - 64] = make_float2(c, s);
    }
    const float2* zp = g_zl + (size_t)zo * 5530;
    for (int idx = t; idx < 5530; idx += blockDim.x) zs[idx] = zp[idx];
    float bv = bias[o];
    float* op = out + (size_t)zo * 64000;
    __syncthreads();

    for (int bl = 0; bl < 20; bl++) {
        int b = bh * 20 + bl;
        const float* dB = g_dh + b * 5530;
        // G[m][j] = sum_l zl * d   (j = n mod 40; j=20 zero)
        for (int e = t; e < 800; e += blockDim.x) {
            int m = e / 40, j = e % 40;
            int n = (j <= 19) ? j : j - 40;
            int an = n < 0 ? -n : n;
            int lmin = m > an ? m : an;
            float gr = 0.0f, gi = 0.0f;
            for (int l = lmin; l < 20; l++) {
                int idx = c_hoff[l] + m*(2*l + 1) + (n + l);
                float d = dB[idx];
                float2 zv = zs[idx];
                gr += zv.x * d; gi += zv.y * d;
            }
            G[e] = make_float2(gr, gi);
        }
        __syncthreads();
        // stage1a: Y[m][r][u] = sum_q G[m][5q+r] w8^{qu}
        for (int e = t; e < 800; e += blockDim.x) {
            int u = e & 7, mr = e >> 3;
            int m = mr / 5, r = mr % 5;
            float yr = 0.0f, yi = 0.0f;
            #pragma unroll
            for (int q = 0; q < 8; q++) {
                float2 gv = G[m*40 + 5*q + r];
                float2 w = w8s[(q*u) & 7];
                yr += gv.x*w.x - gv.y*w.y;
                yi += gv.x*w.y + gv.y*w.x;
            }
            Y[e] = make_float2(yr, yi);
        }
        __syncthreads();
        // stage1b: H[m][g] = scale_m * sum_r tw40[rg] Y[m][r][g mod 8]
        for (int e = t; e < 800; e += blockDim.x) {
            int m = e / 40, g = e % 40;
            int u = g & 7;
            float hr = 0.0f, hi = 0.0f;
            int k = 0;
            #pragma unroll
            for (int r = 0; r < 5; r++) {
                float2 w = tw[k];
                float2 yv = Y[(m*5 + r)*8 + u];
                hr += yv.x*w.x - yv.y*w.y;
                hi += yv.x*w.y + yv.y*w.x;
                k += g; if (k >= 40) k -= 40;
            }
            float sc = (m == 0) ? 0.5f : 1.0f;
            H[e] = make_float2(hr*sc, hi*sc);
        }
        __syncthreads();
        // stage2a: Z[r2][u][g] = sum_q2 H[5q2+r2][g] w8^{q2 u}
        for (int e = t; e < 1600; e += blockDim.x) {
            int g = e % 40, ru = e / 40;
            int r2 = ru >> 3, u = ru & 7;
            float zr = 0.0f, zi = 0.0f;
            #pragma unroll
            for (int q2 = 0; q2 < 4; q2++) {
                float2 hv = H[(5*q2 + r2)*40 + g];
                float2 w = w8s[(q2*u) & 7];
                zr += hv.x*w.x - hv.y*w.y;
                zi += hv.x*w.y + hv.y*w.x;
            }
            Z[(r2*8 + u)*40 + g] = make_float2(zr, zi);
        }
        __syncthreads();
        // stage2b: out[a][g] = 2 Re sum_r2 tw40[r2 a] Z[r2][a mod 8][g] + bias
        for (int e = t; e < 1600; e += blockDim.x) {
            int a = e / 40, g = e % 40;
            int u = a & 7;
            float acc = 0.0f;
            int k = 0;
            #pragma unroll
            for (int r2 = 0; r2 < 5; r2++) {
                float2 w = tw[k];
                float2 zv = Z[(r2*8 + u)*40 + g];
                acc += zv.x*w.x - zv.y*w.y;
                k += a; if (k >= 40) k -= 40;
            }
            op[(b*40 + a)*40 + g] = 2.0f*acc + bv;
        }
        __syncthreads();
    }
}

// ---------- launch ----------
extern "C" void kernel_launch(void* const* d_in, const int* in_sizes, int n_in,
                              void* d_out, int out_size) {
    const float* x    = (const float*)d_in[0];
    const float* kern = (const float*)d_in[1];
    const float* bias = (const float*)d_in[2];
    float* out = (float*)d_out;

    cudaFuncSetAttribute(k_zl,  cudaFuncAttributeMaxDynamicSharedMemorySize, 105600);
    cudaFuncSetAttribute(k_out, cudaFuncAttributeMaxDynamicSharedMemorySize, 76640);

    k_init<<<193, 128>>>();
    k_dft<<<dim3(16, 256), 256>>>(x);
    k_xl2<<<dim3(20, 16), 256>>>();
    k_cy <<<400, 512>>>(kern);
    k_zl <<<dim3(32, 16), 256, 105600>>>();
    k_out<<<dim3(32, 16, 2), 512, 76640>>>(bias, out);
}

// round 6
// speedup vs baseline: 1.7173x; 1.0936x over previous
#include <cuda_runtime.h>
#include <math.h>
#include <stdint.h>

#define PI_D 3.14159265358979323846

// B_IN=64, B_OUT=20, B_INV=20, BATCH=16, F_IN=16, F_OUT=32, N_GRID=24
// half-pair count: sum_l (l+1)(2l+1) = 5530

__constant__ int c_hoff[20]  = {0,1,7,22,50,95,161,252,372,525,715,946,1222,1547,1925,2360,2856,3417,4047,4750};
__constant__ int c_hstep[20] = {1,6,15,28,45,66,91,120,153,190,231,276,325,378,435,496,561,630,703,780};

__device__ float  g_ws2[128*400];      // [beta_b][lm]  lm = l*l + (m+l)
__device__ float2 g_cFk[24*400];       // conj(F_k) [p][lm]
__device__ float  g_dh[40*5530];       // (2l+1)*d^l_{m,n}(beta_b), m>=0 half, [b][hpair]
__device__ unsigned int g_pinfo[5530]; // (l<<12)|(m<<6)|ni
__device__ float2 g_tw[128*20];        // [a][m] e^{-2pi i a m/128}
__device__ float2 g_Xf[20*128*256];    // [m][b][zi]
__device__ float2 g_xl[16*400*16];     // [z][lm][i]
__device__ float2 g_cy[32*400*16];     // [o][lm][i]
__device__ float2 g_zl[512*5530];      // [zo][hpair]

// ---------- fp32 Wigner-d: log-space seed + upward 3-term recurrence ----------
__device__ __forceinline__ float wseed(int m, int n, float lcb, float lsb, const float* lf) {
    int am = m < 0 ? -m : m, an = n < 0 ? -n : n;
    int l = am > an ? am : an;
    float v;
    if (am >= an) {
        float lc = 0.5f*(lf[2*l] - lf[l+n] - lf[l-n]);
        if (m >= 0) { v = expf(lc + (l+n)*lcb + (l-n)*lsb); if ((l-n)&1) v = -v; }
        else        { v = expf(lc + (l-n)*lcb + (l+n)*lsb); }
    } else {
        float lc = 0.5f*(lf[2*l] - lf[l+m] - lf[l-m]);
        if (n >= 0) { v = expf(lc + (l+m)*lcb + (l-m)*lsb); }
        else        { v = expf(lc + (l-m)*lcb + (l+m)*lsb); if ((l+m)&1) v = -v; }
    }
    return v;
}

// ---------- combined init kernel ----------
// blocks 0..127: w_s2; 128..151: cFk; 152..191: dh; 192: pinfo + tw
__global__ void k_init() {
    __shared__ float lf[41];
    __shared__ double sterm[64];
    __shared__ double swq;
    int t = threadIdx.x;
    if (t <= 40) lf[t] = lgammaf((float)(t + 1));
    int blk = blockIdx.x;

    if (blk < 128) {
        int b = blk;
        double beta = PI_D * (2.0*b + 1.0) / 256.0;
        if (t < 64) sterm[t] = sin((2.0*t + 1.0) * beta) / (2.0*t + 1.0);
        __syncthreads();
        if (t == 0) {
            double acc = 0.0;
            for (int k = 0; k < 64; k++) acc += sterm[k];
            swq = (2.0/64.0) * sin(beta) * acc;
        }
        __syncthreads();
        float w = (float)swq;
        float cb = (float)cos(beta*0.5), sb = (float)sin(beta*0.5);
        float cosb = (float)cos(beta);
        float lcb = logf(cb), lsb = logf(sb);
        if (t < 39) {
            int m = t - 19;
            int am = m < 0 ? -m : m;
            int l0 = am;
            float d1 = wseed(m, 0, lcb, lsb, lf), d2 = 0.0f;
            g_ws2[b*400 + l0*l0 + l0 + m] = d1 * w;
            int jstart = l0 + 1;
            if (l0 == 0) {              // m=0 chain: seed analytically past 0/0 step
                d2 = d1; d1 = cosb;
                g_ws2[b*400 + 2] = d1 * w;
                jstart = 2;
            }
            for (int j = jstart; j <= 19; j++) {
                float wj  = sqrtf((float)((j*j - m*m) * (j*j)));
                float wj1 = sqrtf((float)(((j-1)*(j-1) - m*m) * ((j-1)*(j-1))));
                float d = ((2*j-1)*((float)(j*(j-1))*cosb) * d1 - (float)j*wj1*d2) / ((float)(j-1)*wj);
                g_ws2[b*400 + j*j + j + m] = d * w;
                d2 = d1; d1 = d;
            }
        }
    } else if (blk < 152) {
        int p = blk - 128;
        __syncthreads();
        double beta  = ((p >> 3) + 1) * PI_D / 24.0;
        float cb = (float)cos(beta*0.5), sb = (float)sin(beta*0.5);
        float cosb = (float)cos(beta);
        float lcb = logf(cb), lsb = logf(sb);
        if (t < 39) {
            int m = t - 19;
            int am = m < 0 ? -m : m;
            int l0 = am;
            float cph, sph;
            sincospif((float)(m * (p & 7)) * 0.25f, &sph, &cph);
            float d1 = wseed(m, 0, lcb, lsb, lf), d2 = 0.0f;
            g_cFk[p*400 + l0*l0 + l0 + m] = make_float2(d1*cph, d1*sph);
            int jstart = l0 + 1;
            if (l0 == 0) {
                d2 = d1; d1 = cosb;
                g_cFk[p*400 + 2] = make_float2(d1*cph, d1*sph);
                jstart = 2;
            }
            for (int j = jstart; j <= 19; j++) {
                float wj  = sqrtf((float)((j*j - m*m) * (j*j)));
                float wj1 = sqrtf((float)(((j-1)*(j-1) - m*m) * ((j-1)*(j-1))));
                float d = ((2*j-1)*((float)(j*(j-1))*cosb) * d1 - (float)j*wj1*d2) / ((float)(j-1)*wj);
                g_cFk[p*400 + j*j + j + m] = make_float2(d*cph, d*sph);
                d2 = d1; d1 = d;
            }
        }
    } else if (blk < 192) {
        int b = blk - 152;
        __syncthreads();
        double beta = PI_D * (2.0*b + 1.0) / 80.0;
        float cb = (float)cos(beta*0.5), sb = (float)sin(beta*0.5);
        float cosb = (float)cos(beta);
        float lcb = logf(cb), lsb = logf(sb);
        for (int p = t; p < 780; p += blockDim.x) {
            int m = p / 39, nj = p % 39, n = nj - 19;
            int an = n < 0 ? -n : n;
            int l0 = m > an ? m : an;
            float d1 = wseed(m, n, lcb, lsb, lf), d2 = 0.0f;
            g_dh[b*5530 + c_hoff[l0] + m*(2*l0+1) + n + l0] = (float)(2*l0+1) * d1;
            int jstart = l0 + 1;
            if (l0 == 0) {
                d2 = d1; d1 = cosb;
                g_dh[b*5530 + c_hoff[1] + 1] = 3.0f * d1;
                jstart = 2;
            }
            float mn = (float)(m * n);
            for (int j = jstart; j <= 19; j++) {
                float wj  = sqrtf((float)((j*j - m*m) * (j*j - n*n)));
                float wj1 = sqrtf((float)(((j-1)*(j-1) - m*m) * ((j-1)*(j-1) - n*n)));
                float d = ((2*j-1)*((float)(j*(j-1))*cosb - mn) * d1 - (float)j*wj1*d2) / ((float)(j-1)*wj);
                g_dh[b*5530 + c_hoff[j] + m*(2*j+1) + n + j] = (float)(2*j+1) * d;
                d2 = d1; d1 = d;
            }
        }
    } else {
        __syncthreads();
        for (int p = t; p < 5530; p += blockDim.x) {
            int l = 0, acc = 0;
            for (; l < 20; l++) {
                int sz = (l+1)*(2*l+1);
                if (p < acc + sz) break;
                acc += sz;
            }
            int r = p - acc, w = 2*l + 1;
            g_pinfo[p] = (unsigned)((l << 12) | ((r / w) << 6) | (r % w));
        }
        for (int idx = t; idx < 2560; idx += blockDim.x) {
            int a = idx / 20, m = idx % 20;
            float s, c;
            sincospif(-(float)(a * m) / 64.0f, &s, &c);   // e^{-2 pi i a m / 128}
            g_tw[idx] = make_float2(c, s);
        }
    }
}

// ---------- K1: truncated real DFT over alpha via twiddle table ----------
// grid (8, 256), block 160: 16 betas per block, item = (beta-pair, m)
__global__ void k_dft(const float* __restrict__ x) {
    __shared__ float  xs[16][130];     // padded rows: conflict-free cross-row reads
    __shared__ float2 tws[128*20];
    int bg = blockIdx.x, zi = blockIdx.y;
    const float* xp = x + (zi * 128 + bg * 16) * 128;
    for (int idx = threadIdx.x; idx < 2048; idx += 160)
        xs[idx >> 7][idx & 127] = xp[idx];
    for (int idx = threadIdx.x; idx < 2560; idx += 160)
        tws[idx] = g_tw[idx];
    __syncthreads();
    int bp = threadIdx.x / 20;     // 0..7 (beta pair)
    int m  = threadIdx.x % 20;
    const float* r0 = xs[2*bp];
    const float* r1 = xs[2*bp + 1];
    float a0r = 0.f, a0i = 0.f, a1r = 0.f, a1i = 0.f;
    #pragma unroll 4
    for (int a = 0; a < 128; a++) {
        float2 w = tws[a*20 + m];
        float x0 = r0[a], x1 = r1[a];
        a0r += x0*w.x; a0i += x0*w.y;
        a1r += x1*w.x; a1i += x1*w.y;
    }
    int b = bg * 16 + 2*bp;
    g_Xf[(m*128 + b    )*256 + zi] = make_float2(a0r, a0i);
    g_Xf[(m*128 + b + 1)*256 + zi] = make_float2(a1r, a1i);
}

// ---------- K2: S2 analysis, tiled by (|m|, z) ----------
__global__ void k_xl2() {
    __shared__ float2 Xs[128*16];
    __shared__ float wsp[128*20];
    __shared__ float wsm[128*20];
    int ma = blockIdx.x, z = blockIdx.y;
    int nl = 20 - ma;
    int t = threadIdx.x;
    for (int idx = t; idx < 2048; idx += 256) {
        int b = idx >> 4, i = idx & 15;
        Xs[idx] = g_Xf[(ma*128 + b)*256 + z*16 + i];
    }
    for (int idx = t; idx < 128*nl; idx += 256) {
        int b = idx / nl, li = idx % nl;
        int l = ma + li;
        wsp[idx] = g_ws2[b*400 + l*l + l + ma];
        if (ma > 0) wsm[idx] = g_ws2[b*400 + l*l + l - ma];
    }
    __syncthreads();
    for (int item = t; item < nl*16; item += 256) {
        int li = item >> 4, i = item & 15;
        int l = ma + li;
        float pr = 0.f, pi = 0.f, mr = 0.f, mi = 0.f;
        for (int b = 0; b < 128; b++) {
            float2 xv = Xs[b*16 + i];
            float wp = wsp[b*nl + li];
            pr += wp * xv.x; pi += wp * xv.y;
            if (ma > 0) {
                float wm = wsm[b*nl + li];
                mr += wm * xv.x; mi -= wm * xv.y;
            }
        }
        g_xl[((size_t)z*400 + l*l + l + ma)*16 + i] = make_float2(pr, pi);
        if (ma > 0)
            g_xl[((size_t)z*400 + l*l + l - ma)*16 + i] = make_float2(mr, mi);
    }
}

// ---------- K3: cy = SCALING * conj(y) ----------
__global__ void k_cy(const float* __restrict__ kern) {
    __shared__ float2 sF[24];
    int lm = blockIdx.x;
    if (threadIdx.x < 24) sF[threadIdx.x] = g_cFk[threadIdx.x * 400 + lm];
    __syncthreads();
    int i = threadIdx.x >> 5, o = threadIdx.x & 31;
    const float* kp = kern + (i * 32 + o) * 24;
    float ar = 0.0f, ai = 0.0f;
    for (int p = 0; p < 24; p++) {
        float k = kp[p];
        ar += k * sF[p].x; ai += k * sF[p].y;
    }
    const float S = 0.00816496580927726f;  // 1/sqrt(15000)
    g_cy[((size_t)o * 400 + lm) * 16 + i] = make_float2(ar * S, ai * S);
}

// ---------- K4: zl[zo][hpair] ----------
__global__ void k_zl() {
    extern __shared__ float2 sm4[];
    float2* xs = sm4;
    float2* cs = sm4 + 6400;
    int o = blockIdx.x, z = blockIdx.y;
    for (int idx = threadIdx.x; idx < 6400; idx += blockDim.x) {
        xs[idx] = g_xl[(size_t)z * 6400 + idx];
        int lm = idx >> 4, i = idx & 15;
        cs[lm * 17 + i] = g_cy[(size_t)o * 6400 + idx];
    }
    __syncthreads();
    float2* outp = g_zl + (size_t)(z * 32 + o) * 5530;
    for (int p = threadIdx.x; p < 5530; p += blockDim.x) {
        unsigned info = g_pinfo[p];
        int l = info >> 12, m = (info >> 6) & 63, ni = info & 63;
        const float2* A  = xs + (l*l + l + m) * 16;
        const float2* Bc = cs + (l*l + ni) * 17;
        float ar = 0.0f, ai = 0.0f;
        #pragma unroll
        for (int i = 0; i < 16; i++) {
            float2 a = A[i], c = Bc[i];
            ar += a.x*c.x - a.y*c.y;
            ai += a.x*c.y + a.y*c.x;
        }
        outp[p] = make_float2(ar, ai);
    }
}

// ---------- K5: fused G-build + factorized synthesis, 2 betas per barrier group ----------
__global__ void k_out(const float* __restrict__ bias, float* __restrict__ out) {
    extern __shared__ float smemraw[];
    float2* zs  = (float2*)smemraw;          // 5530
    float2* G   = zs + 5530;                 // 2 x [m 20][j 40]
    float2* Y   = G + 1600;                  // 2 x 800
    float2* H   = Y + 1600;                  // 2 x 800
    float2* Z   = H + 1600;                  // 2 x 1600
    float2* tw  = Z + 3200;                  // 40
    float2* w8s = tw + 40;                   // 8
    int o = blockIdx.x, z = blockIdx.y, bh = blockIdx.z;
    int zo = z * 32 + o;
    int t = threadIdx.x;
    if (t < 40) {
        float s, c;
        sincospif((float)t / 20.0f, &s, &c);
        tw[t] = make_float2(c, s);
    }
    if (t >= 64 && t < 72) {
        float s, c;
        sincospif((float)(t - 64) * 0.25f, &s, &c);
        w8s[t - 64] = make_float2(c, s);
    }
    const float2* zp = g_zl + (size_t)zo * 5530;
    for (int idx = t; idx < 5530; idx += blockDim.x) zs[idx] = zp[idx];
    float bv = bias[o];
    float* op = out + (size_t)zo * 64000;
    __syncthreads();

    for (int bl = 0; bl < 10; bl++) {
        int b0 = bh * 20 + bl * 2;
        const float* dB0 = g_dh + b0 * 5530;
        const float* dB1 = dB0 + 5530;
        // G[pr][m][j] = sum_l zl * d   (j = n mod 40; j=20 zero)
        for (int e = t; e < 1600; e += blockDim.x) {
            int pr = e / 800, e8 = e - pr*800;
            const float* dB = pr ? dB1 : dB0;
            int m = e8 / 40, j = e8 % 40;
            int n = (j <= 19) ? j : j - 40;
            int an = n < 0 ? -n : n;
            int lmin = m > an ? m : an;
            int idx = c_hoff[lmin] + m*(2*lmin + 1) + (n + lmin);
            int inc = 2*m + 1;
            float gr = 0.0f, gi = 0.0f;
            for (int l = lmin; l < 20; l++) {
                float d = dB[idx];
                float2 zv = zs[idx];
                gr += zv.x * d; gi += zv.y * d;
                idx += c_hstep[l] + inc;
            }
            G[e] = make_float2(gr, gi);
        }
        __syncthreads();
        // stage1a: Y[pr][m][r][u] = sum_q G[pr][m][5q+r] w8^{qu}
        for (int e = t; e < 1600; e += blockDim.x) {
            int pr = e / 800, e8 = e - pr*800;
            int u = e8 & 7, mr = e8 >> 3;
            int m = mr / 5, r = mr % 5;
            const float2* Gp = G + pr*800 + m*40;
            float yr = 0.0f, yi = 0.0f;
            #pragma unroll
            for (int q = 0; q < 8; q++) {
                float2 gv = Gp[5*q + r];
                float2 w = w8s[(q*u) & 7];
                yr += gv.x*w.x - gv.y*w.y;
                yi += gv.x*w.y + gv.y*w.x;
            }
            Y[e] = make_float2(yr, yi);
        }
        __syncthreads();
        // stage1b: H[pr][m][g] = scale_m * sum_r tw40[rg] Y[pr][m][r][g mod 8]
        for (int e = t; e < 1600; e += blockDim.x) {
            int pr = e / 800, e8 = e - pr*800;
            int m = e8 / 40, g = e8 % 40;
            int u = g & 7;
            const float2* Yp = Y + pr*800 + m*40;
            float hr = 0.0f, hi = 0.0f;
            int k = 0;
            #pragma unroll
            for (int r = 0; r < 5; r++) {
                float2 w = tw[k];
                float2 yv = Yp[r*8 + u];
                hr += yv.x*w.x - yv.y*w.y;
                hi += yv.x*w.y + yv.y*w.x;
                k += g; if (k >= 40) k -= 40;
            }
            float sc = (m == 0) ? 0.5f : 1.0f;
            H[e] = make_float2(hr*sc, hi*sc);
        }
        __syncthreads();
        // stage2a: Z[pr][r2][u][g] = sum_q2 H[pr][5q2+r2][g] w8^{q2 u}
        for (int e = t; e < 3200; e += blockDim.x) {
            int pr = e / 1600, e16 = e - pr*1600;
            int g = e16 % 40, ru = e16 / 40;
            int r2 = ru >> 3, u = ru & 7;
            const float2* Hp = H + pr*800;
            float zr = 0.0f, zi = 0.0f;
            #pragma unroll
            for (int q2 = 0; q2 < 4; q2++) {
                float2 hv = Hp[(5*q2 + r2)*40 + g];
                float2 w = w8s[(q2*u) & 7];
                zr += hv.x*w.x - hv.y*w.y;
                zi += hv.x*w.y + hv.y*w.x;
            }
            Z[pr*1600 + (r2*8 + u)*40 + g] = make_float2(zr, zi);
        }
        __syncthreads();
        // stage2b: out[a][g] = 2 Re sum_r2 tw40[r2 a] Z[pr][r2][a mod 8][g] + bias
        for (int e = t; e < 3200; e += blockDim.x) {
            int pr = e / 1600, e16 = e - pr*1600;
            int a = e16 / 40, g = e16 % 40;
            int u = a & 7;
            const float2* Zp = Z + pr*1600;
            float acc = 0.0f;
            int k = 0;
            #pragma unroll
            for (int r2 = 0; r2 < 5; r2++) {
                float2 w = tw[k];
                float2 zv = Zp[(r2*8 + u)*40 + g];
                acc += zv.x*w.x - zv.y*w.y;
                k += a; if (k >= 40) k -= 40;
            }
            op[((b0 + pr)*40 + a)*40 + g] = 2.0f*acc + bv;
        }
        __syncthreads();
    }
}

// ---------- launch ----------
extern "C" void kernel_launch(void* const* d_in, const int* in_sizes, int n_in,
                              void* d_out, int out_size) {
    const float* x    = (const float*)d_in[0];
    const float* kern = (const float*)d_in[1];
    const float* bias = (const float*)d_in[2];
    float* out = (float*)d_out;

    cudaFuncSetAttribute(k_zl,  cudaFuncAttributeMaxDynamicSharedMemorySize, 105600);
    cudaFuncSetAttribute(k_out, cudaFuncAttributeMaxDynamicSharedMemorySize, 108624);

    k_init<<<193, 128>>>();
    k_dft<<<dim3(8, 256), 160>>>(x);
    k_xl2<<<dim3(20, 16), 256>>>();
    k_cy <<<400, 512>>>(kern);
    k_zl <<<dim3(32, 16), 256, 105600>>>();
    k_out<<<dim3(32, 16, 2), 512, 108624>>>(bias, out);
}

// round 8
// speedup vs baseline: 1.8920x; 1.1017x over previous
#include <cuda_runtime.h>
#include <math.h>
#include <stdint.h>

#define PI_D 3.14159265358979323846

// B_IN=64, B_OUT=20, B_INV=20, BATCH=16, F_IN=16, F_OUT=32, N_GRID=24
// half-pair count: sum_l (l+1)(2l+1) = 5530

__constant__ int c_hoff[20]  = {0,1,7,22,50,95,161,252,372,525,715,946,1222,1547,1925,2360,2856,3417,4047,4750};
__constant__ int c_hstep[20] = {1,6,15,28,45,66,91,120,153,190,231,276,325,378,435,496,561,630,703,780};

__device__ float  g_ws2[128*400];      // [beta_b][lm]  lm = l*l + (m+l)
__device__ float2 g_cFk[24*400];       // conj(F_k) [p][lm]
__device__ float  g_dh[40*5530];       // (2l+1)*d^l_{m,n}(beta_b), m>=0 half, [b][hpair]
__device__ unsigned int g_pinfo[5530]; // (l<<12)|(m<<6)|ni
__device__ float2 g_tw[128*20];        // [a][m] e^{-2pi i a m/128}
__device__ float2 g_Xf[20*128*256];    // [m][b][zi]
__device__ float2 g_xl[16*400*16];     // [z][lm][i]
__device__ float2 g_cy[32*400*16];     // [o][lm][i]
__device__ float2 g_zl[512*5530];      // [zo][hpair]
__device__ float2 g_H[512*40*800];     // [zo][b][g][m]  (131 MB intermediate)

// e^{+2pi i k/40} tables (static-index use only -> folded to immediates)
__device__ static constexpr float TWC[40] = {
 1.0f, 0.98768834f, 0.95105652f, 0.89100652f, 0.80901699f, 0.70710678f,
 0.58778525f, 0.45399050f, 0.30901699f, 0.15643447f, 0.0f, -0.15643447f,
 -0.30901699f, -0.45399050f, -0.58778525f, -0.70710678f, -0.80901699f,
 -0.89100652f, -0.95105652f, -0.98768834f, -1.0f, -0.98768834f, -0.95105652f,
 -0.89100652f, -0.80901699f, -0.70710678f, -0.58778525f, -0.45399050f,
 -0.30901699f, -0.15643447f, 0.0f, 0.15643447f, 0.30901699f, 0.45399050f,
 0.58778525f, 0.70710678f, 0.80901699f, 0.89100652f, 0.95105652f, 0.98768834f };
__device__ static constexpr float TWS[40] = {
 0.0f, 0.15643447f, 0.30901699f, 0.45399050f, 0.58778525f, 0.70710678f,
 0.80901699f, 0.89100652f, 0.95105652f, 0.98768834f, 1.0f, 0.98768834f,
 0.95105652f, 0.89100652f, 0.80901699f, 0.70710678f, 0.58778525f,
 0.45399050f, 0.30901699f, 0.15643447f, 0.0f, -0.15643447f, -0.30901699f,
 -0.45399050f, -0.58778525f, -0.70710678f, -0.80901699f, -0.89100652f,
 -0.95105652f, -0.98768834f, -1.0f, -0.98768834f, -0.95105652f, -0.89100652f,
 -0.80901699f, -0.70710678f, -0.58778525f, -0.45399050f, -0.30901699f,
 -0.15643447f };

__device__ __forceinline__ float2 cadd(float2 a, float2 b){ return make_float2(a.x+b.x, a.y+b.y); }
__device__ __forceinline__ float2 csub(float2 a, float2 b){ return make_float2(a.x-b.x, a.y-b.y); }
__device__ __forceinline__ float2 cmuli(float2 a){ return make_float2(-a.y, a.x); }      // *i
__device__ __forceinline__ float2 cmulc(float2 a, float c, float s){                     // *(c+is)
    return make_float2(a.x*c - a.y*s, a.x*s + a.y*c);
}

// ---------- fp32 Wigner-d: log-space seed + upward 3-term recurrence ----------
__device__ __forceinline__ float wseed(int m, int n, float lcb, float lsb, const float* lf) {
    int am = m < 0 ? -m : m, an = n < 0 ? -n : n;
    int l = am > an ? am : an;
    float v;
    if (am >= an) {
        float lc = 0.5f*(lf[2*l] - lf[l+n] - lf[l-n]);
        if (m >= 0) { v = expf(lc + (l+n)*lcb + (l-n)*lsb); if ((l-n)&1) v = -v; }
        else        { v = expf(lc + (l-n)*lcb + (l+n)*lsb); }
    } else {
        float lc = 0.5f*(lf[2*l] - lf[l+m] - lf[l-m]);
        if (n >= 0) { v = expf(lc + (l+m)*lcb + (l-m)*lsb); }
        else        { v = expf(lc + (l-m)*lcb + (l+m)*lsb); if ((l+m)&1) v = -v; }
    }
    return v;
}

// ---------- combined init kernel ----------
__global__ void k_init() {
    __shared__ float lf[41];
    __shared__ double sterm[64];
    __shared__ double swq;
    int t = threadIdx.x;
    if (t <= 40) lf[t] = lgammaf((float)(t + 1));
    int blk = blockIdx.x;

    if (blk < 128) {
        int b = blk;
        double beta = PI_D * (2.0*b + 1.0) / 256.0;
        if (t < 64) sterm[t] = sin((2.0*t + 1.0) * beta) / (2.0*t + 1.0);
        __syncthreads();
        if (t == 0) {
            double acc = 0.0;
            for (int k = 0; k < 64; k++) acc += sterm[k];
            swq = (2.0/64.0) * sin(beta) * acc;
        }
        __syncthreads();
        float w = (float)swq;
        float cb = (float)cos(beta*0.5), sb = (float)sin(beta*0.5);
        float cosb = (float)cos(beta);
        float lcb = logf(cb), lsb = logf(sb);
        if (t < 39) {
            int m = t - 19;
            int am = m < 0 ? -m : m;
            int l0 = am;
            float d1 = wseed(m, 0, lcb, lsb, lf), d2 = 0.0f;
            g_ws2[b*400 + l0*l0 + l0 + m] = d1 * w;
            int jstart = l0 + 1;
            if (l0 == 0) {
                d2 = d1; d1 = cosb;
                g_ws2[b*400 + 2] = d1 * w;
                jstart = 2;
            }
            for (int j = jstart; j <= 19; j++) {
                float wj  = sqrtf((float)((j*j - m*m) * (j*j)));
                float wj1 = sqrtf((float)(((j-1)*(j-1) - m*m) * ((j-1)*(j-1))));
                float d = ((2*j-1)*((float)(j*(j-1))*cosb) * d1 - (float)j*wj1*d2) / ((float)(j-1)*wj);
                g_ws2[b*400 + j*j + j + m] = d * w;
                d2 = d1; d1 = d;
            }
        }
    } else if (blk < 152) {
        int p = blk - 128;
        __syncthreads();
        double beta  = ((p >> 3) + 1) * PI_D / 24.0;
        float cb = (float)cos(beta*0.5), sb = (float)sin(beta*0.5);
        float cosb = (float)cos(beta);
        float lcb = logf(cb), lsb = logf(sb);
        if (t < 39) {
            int m = t - 19;
            int am = m < 0 ? -m : m;
            int l0 = am;
            float cph, sph;
            sincospif((float)(m * (p & 7)) * 0.25f, &sph, &cph);
            float d1 = wseed(m, 0, lcb, lsb, lf), d2 = 0.0f;
            g_cFk[p*400 + l0*l0 + l0 + m] = make_float2(d1*cph, d1*sph);
            int jstart = l0 + 1;
            if (l0 == 0) {
                d2 = d1; d1 = cosb;
                g_cFk[p*400 + 2] = make_float2(d1*cph, d1*sph);
                jstart = 2;
            }
            for (int j = jstart; j <= 19; j++) {
                float wj  = sqrtf((float)((j*j - m*m) * (j*j)));
                float wj1 = sqrtf((float)(((j-1)*(j-1) - m*m) * ((j-1)*(j-1))));
                float d = ((2*j-1)*((float)(j*(j-1))*cosb) * d1 - (float)j*wj1*d2) / ((float)(j-1)*wj);
                g_cFk[p*400 + j*j + j + m] = make_float2(d*cph, d*sph);
                d2 = d1; d1 = d;
            }
        }
    } else if (blk < 192) {
        int b = blk - 152;
        __syncthreads();
        double beta = PI_D * (2.0*b + 1.0) / 80.0;
        float cb = (float)cos(beta*0.5), sb = (float)sin(beta*0.5);
        float cosb = (float)cos(beta);
        float lcb = logf(cb), lsb = logf(sb);
        for (int p = t; p < 780; p += blockDim.x) {
            int m = p / 39, nj = p % 39, n = nj - 19;
            int an = n < 0 ? -n : n;
            int l0 = m > an ? m : an;
            float d1 = wseed(m, n, lcb, lsb, lf), d2 = 0.0f;
            g_dh[b*5530 + c_hoff[l0] + m*(2*l0+1) + n + l0] = (float)(2*l0+1) * d1;
            int jstart = l0 + 1;
            if (l0 == 0) {
                d2 = d1; d1 = cosb;
                g_dh[b*5530 + c_hoff[1] + 1] = 3.0f * d1;
                jstart = 2;
            }
            float mn = (float)(m * n);
            for (int j = jstart; j <= 19; j++) {
                float wj  = sqrtf((float)((j*j - m*m) * (j*j - n*n)));
                float wj1 = sqrtf((float)(((j-1)*(j-1) - m*m) * ((j-1)*(j-1) - n*n)));
                float d = ((2*j-1)*((float)(j*(j-1))*cosb - mn) * d1 - (float)j*wj1*d2) / ((float)(j-1)*wj);
                g_dh[b*5530 + c_hoff[j] + m*(2*j+1) + n + j] = (float)(2*j+1) * d;
                d2 = d1; d1 = d;
            }
        }
    } else {
        __syncthreads();
        for (int p = t; p < 5530; p += blockDim.x) {
            int l = 0, acc = 0;
            for (; l < 20; l++) {
                int sz = (l+1)*(2*l+1);
                if (p < acc + sz) break;
                acc += sz;
            }
            int r = p - acc, w = 2*l + 1;
            g_pinfo[p] = (unsigned)((l << 12) | ((r / w) << 6) | (r % w));
        }
        for (int idx = t; idx < 2560; idx += blockDim.x) {
            int a = idx / 20, m = idx % 20;
            float s, c;
            sincospif(-(float)(a * m) / 64.0f, &s, &c);
            g_tw[idx] = make_float2(c, s);
        }
    }
}

// ---------- K1: truncated real DFT over alpha via twiddle table ----------
__global__ void k_dft(const float* __restrict__ x) {
    __shared__ float  xs[16][130];
    __shared__ float2 tws[128*20];
    int bg = blockIdx.x, zi = blockIdx.y;
    const float* xp = x + (zi * 128 + bg * 16) * 128;
    for (int idx = threadIdx.x; idx < 2048; idx += 160)
        xs[idx >> 7][idx & 127] = xp[idx];
    for (int idx = threadIdx.x; idx < 2560; idx += 160)
        tws[idx] = g_tw[idx];
    __syncthreads();
    int bp = threadIdx.x / 20;
    int m  = threadIdx.x % 20;
    const float* r0 = xs[2*bp];
    const float* r1 = xs[2*bp + 1];
    float a0r = 0.f, a0i = 0.f, a1r = 0.f, a1i = 0.f;
    #pragma unroll 4
    for (int a = 0; a < 128; a++) {
        float2 w = tws[a*20 + m];
        float x0 = r0[a], x1 = r1[a];
        a0r += x0*w.x; a0i += x0*w.y;
        a1r += x1*w.x; a1i += x1*w.y;
    }
    int b = bg * 16 + 2*bp;
    g_Xf[(m*128 + b    )*256 + zi] = make_float2(a0r, a0i);
    g_Xf[(m*128 + b + 1)*256 + zi] = make_float2(a1r, a1i);
}

// ---------- K2: S2 analysis, tiled by (|m|, z) ----------
__global__ void k_xl2() {
    __shared__ float2 Xs[128*16];
    __shared__ float wsp[128*20];
    __shared__ float wsm[128*20];
    int ma = blockIdx.x, z = blockIdx.y;
    int nl = 20 - ma;
    int t = threadIdx.x;
    for (int idx = t; idx < 2048; idx += 256) {
        int b = idx >> 4, i = idx & 15;
        Xs[idx] = g_Xf[(ma*128 + b)*256 + z*16 + i];
    }
    for (int idx = t; idx < 128*nl; idx += 256) {
        int b = idx / nl, li = idx % nl;
        int l = ma + li;
        wsp[idx] = g_ws2[b*400 + l*l + l + ma];
        if (ma > 0) wsm[idx] = g_ws2[b*400 + l*l + l - ma];
    }
    __syncthreads();
    for (int item = t; item < nl*16; item += 256) {
        int li = item >> 4, i = item & 15;
        int l = ma + li;
        float pr = 0.f, pi = 0.f, mr = 0.f, mi = 0.f;
        for (int b = 0; b < 128; b++) {
            float2 xv = Xs[b*16 + i];
            float wp = wsp[b*nl + li];
            pr += wp * xv.x; pi += wp * xv.y;
            if (ma > 0) {
                float wm = wsm[b*nl + li];
                mr += wm * xv.x; mi -= wm * xv.y;
            }
        }
        g_xl[((size_t)z*400 + l*l + l + ma)*16 + i] = make_float2(pr, pi);
        if (ma > 0)
            g_xl[((size_t)z*400 + l*l + l - ma)*16 + i] = make_float2(mr, mi);
    }
}

// ---------- K3: cy = SCALING * conj(y) ----------
__global__ void k_cy(const float* __restrict__ kern) {
    __shared__ float2 sF[24];
    int lm = blockIdx.x;
    if (threadIdx.x < 24) sF[threadIdx.x] = g_cFk[threadIdx.x * 400 + lm];
    __syncthreads();
    int i = threadIdx.x >> 5, o = threadIdx.x & 31;
    const float* kp = kern + (i * 32 + o) * 24;
    float ar = 0.0f, ai = 0.0f;
    for (int p = 0; p < 24; p++) {
        float k = kp[p];
        ar += k * sF[p].x; ai += k * sF[p].y;
    }
    const float S = 0.00816496580927726f;
    g_cy[((size_t)o * 400 + lm) * 16 + i] = make_float2(ar * S, ai * S);
}

// ---------- K4: zl[zo][hpair] ----------
__global__ void k_zl() {
    extern __shared__ float2 sm4[];
    float2* xs = sm4;
    float2* cs = sm4 + 6400;
    int o = blockIdx.x, z = blockIdx.y;
    for (int idx = threadIdx.x; idx < 6400; idx += blockDim.x) {
        xs[idx] = g_xl[(size_t)z * 6400 + idx];
        int lm = idx >> 4, i = idx & 15;
        cs[lm * 17 + i] = g_cy[(size_t)o * 6400 + idx];
    }
    __syncthreads();
    float2* outp = g_zl + (size_t)(z * 32 + o) * 5530;
    for (int p = threadIdx.x; p < 5530; p += blockDim.x) {
        unsigned info = g_pinfo[p];
        int l = info >> 12, m = (info >> 6) & 63, ni = info & 63;
        const float2* A  = xs + (l*l + l + m) * 16;
        const float2* Bc = cs + (l*l + ni) * 17;
        float ar = 0.0f, ai = 0.0f;
        #pragma unroll
        for (int i = 0; i < 16; i++) {
            float2 a = A[i], c = Bc[i];
            ar += a.x*c.x - a.y*c.y;
            ai += a.x*c.y + a.y*c.x;
        }
        outp[p] = make_float2(ar, ai);
    }
}

// ---------- per-thread 40-pt FFT half (u = 4*HH .. 4*HH+3), stage1 ----------
template<int HH>
__device__ __forceinline__ void row_fft40(const float2* __restrict__ Grow,
                                          float2* __restrict__ dst) {
    const float R2 = 0.70710678f;
    float2 T[5][4];
    #pragma unroll
    for (int r = 0; r < 5; r++) {
        float2 x0=Grow[r],    x1=Grow[5+r],  x2=Grow[10+r], x3=Grow[15+r];
        float2 x4=Grow[20+r], x5=Grow[25+r], x6=Grow[30+r], x7=Grow[35+r];
        float2 a04=cadd(x0,x4), s04=csub(x0,x4);
        float2 a26=cadd(x2,x6), s26=csub(x2,x6);
        float2 E0=cadd(a04,a26), E1=cadd(s04,cmuli(s26));
        float2 E2=csub(a04,a26), E3=csub(s04,cmuli(s26));
        float2 a15=cadd(x1,x5), s15=csub(x1,x5);
        float2 a37=cadd(x3,x7), s37=csub(x3,x7);
        float2 O0=cadd(a15,a37), O1=cadd(s15,cmuli(s37));
        float2 O2=csub(a15,a37), O3=csub(s15,cmuli(s37));
        // combine: y[u'] = E[u'] + W8^{u'} O[u'] (HH=0) or E - W8 O (HH=1); then * W40^{r*u}
        float2 w1o = make_float2(R2*(O1.x-O1.y), R2*(O1.x+O1.y));  // W8^1 * O1
        float2 w2o = cmuli(O2);                                     // W8^2 * O2
        float2 w3o = make_float2(-R2*(O3.x+O3.y), R2*(O3.x-O3.y)); // W8^3 * O3
        float2 y0, y1, y2, y3;
        if (HH == 0) { y0=cadd(E0,O0); y1=cadd(E1,w1o); y2=cadd(E2,w2o); y3=cadd(E3,w3o); }
        else         { y0=csub(E0,O0); y1=csub(E1,w1o); y2=csub(E2,w2o); y3=csub(E3,w3o); }
        T[r][0] = cmulc(y0, TWC[(r*(4*HH+0))%40], TWS[(r*(4*HH+0))%40]);
        T[r][1] = cmulc(y1, TWC[(r*(4*HH+1))%40], TWS[(r*(4*HH+1))%40]);
        T[r][2] = cmulc(y2, TWC[(r*(4*HH+2))%40], TWS[(r*(4*HH+2))%40]);
        T[r][3] = cmulc(y3, TWC[(r*(4*HH+3))%40], TWS[(r*(4*HH+3))%40]);
    }
    #pragma unroll
    for (int up = 0; up < 4; up++) {
        int u = 4*HH + up;
        #pragma unroll
        for (int s = 0; s < 5; s++) {
            float2 acc = T[0][up];
            #pragma unroll
            for (int r = 1; r < 5; r++)
                acc = cadd(acc, cmulc(T[r][up], TWC[(8*r*s)%40], TWS[(8*r*s)%40]));
            dst[(8*s + u) * 20] = acc;
        }
    }
}

// ---------- K5a: G-build + stage1 FFT -> H[zo][b][g][m] ----------
__global__ void __launch_bounds__(320, 2) k_h() {
    extern __shared__ float2 sm5[];
    float2* zs = sm5;          // 5530
    float2* Gs = sm5 + 5530;   // 160 rows x 41 (padded)
    int zo = blockIdx.x, bg = blockIdx.y;
    int t = threadIdx.x;
    const float2* zp = g_zl + (size_t)zo * 5530;
    for (int idx = t; idx < 5530; idx += 320) zs[idx] = zp[idx];
    __syncthreads();
    // phase 1: build G for 8 betas
    for (int e = t; e < 6400; e += 320) {
        int bloc = e / 800, rem = e - bloc*800;
        int m = rem / 40, j = rem % 40;
        int b = bg*8 + bloc;
        const float* dB = g_dh + b * 5530;
        int n = (j <= 19) ? j : j - 40;
        int an = n < 0 ? -n : n;
        int lmin = m > an ? m : an;
        int idx = c_hoff[lmin] + m*(2*lmin + 1) + (n + lmin);
        int inc = 2*m + 1;
        float gr = 0.0f, gi = 0.0f;
        for (int l = lmin; l < 20; l++) {
            float d = dB[idx];
            float2 zv = zs[idx];
            gr += zv.x * d; gi += zv.y * d;
            idx += c_hstep[l] + inc;
        }
        Gs[(bloc*20 + m)*41 + j] = make_float2(gr, gi);
    }
    __syncthreads();
    // phase 2: 40-pt FFT per row (2 threads per row, u-halves)
    int h = t / 160, row = t - h*160;
    int b = bg*8 + row/20, m = row % 20;
    const float2* Grow = Gs + row*41;
    float2* dst = g_H + ((size_t)(zo*40 + b))*800 + m;
    if (h == 0) row_fft40<0>(Grow, dst);
    else        row_fft40<1>(Grow, dst);
}

// ---------- K5b: stage2 (m->a, real) + bias -> out ----------
__global__ void __launch_bounds__(320, 2) k_o(const float* __restrict__ bias,
                                              float* __restrict__ out) {
    extern __shared__ float2 sm6[];   // 8 b x 40 g x 21 (padded m)
    int zo = blockIdx.x, bg = blockIdx.y;
    int t = threadIdx.x;
    const float2* Hp = g_H + ((size_t)(zo*40 + bg*8))*800;
    for (int v = t; v < 6400; v += 320) {
        int c20 = v / 20, m = v - c20*20;
        sm6[c20*21 + m] = Hp[v];
    }
    float bv = bias[zo & 31];
    __syncthreads();
    int bloc = t / 40, g = t - bloc*40;
    int b = bg*8 + bloc;
    const float2* col = sm6 + (bloc*40 + g)*21;
    float2 hc[20];
    #pragma unroll
    for (int m = 0; m < 20; m++) hc[m] = col[m];
    hc[0].x *= 0.5f; hc[0].y *= 0.5f;
    float* op = out + (size_t)zo*64000 + b*1600 + g;
    const float R2 = 0.70710678f;
    #pragma unroll
    for (int u = 0; u < 8; u++) {
        float2 B[5];
        #pragma unroll
        for (int r = 0; r < 5; r++) {
            // A[r] = sum_{q=0}^{3} hc[5q+r] * W8^{(q*u)&7}
            float2 acc = hc[r];
            #pragma unroll
            for (int q = 1; q < 4; q++) {
                int k8 = (q*u) & 7;
                float c, s;
                switch (k8) {
                    case 0: c=1.f;  s=0.f;  break;
                    case 1: c=R2;   s=R2;   break;
                    case 2: c=0.f;  s=1.f;  break;
                    case 3: c=-R2;  s=R2;   break;
                    case 4: c=-1.f; s=0.f;  break;
                    case 5: c=-R2;  s=-R2;  break;
                    case 6: c=0.f;  s=-1.f; break;
                    default: c=R2;  s=-R2;  break;
                }
                acc = cadd(acc, cmulc(hc[5*q + r], c, s));
            }
            B[r] = cmulc(acc, TWC[(r*u)%40], TWS[(r*u)%40]);
        }
        #pragma unroll
        for (int s = 0; s < 5; s++) {
            float val = B[0].x;
            #pragma unroll
            for (int r = 1; r < 5; r++)
                val += B[r].x * TWC[(8*r*s)%40] - B[r].y * TWS[(8*r*s)%40];
            op[(8*s + u) * 40] = 2.0f*val + bv;
        }
    }
}

// ---------- launch ----------
extern "C" void kernel_launch(void* const* d_in, const int* in_sizes, int n_in,
                              void* d_out, int out_size) {
    const float* x    = (const float*)d_in[0];
    const float* kern = (const float*)d_in[1];
    const float* bias = (const float*)d_in[2];
    float* out = (float*)d_out;

    cudaFuncSetAttribute(k_zl, cudaFuncAttributeMaxDynamicSharedMemorySize, 105600);
    cudaFuncSetAttribute(k_h,  cudaFuncAttributeMaxDynamicSharedMemorySize, 96720);
    cudaFuncSetAttribute(k_o,  cudaFuncAttributeMaxDynamicSharedMemorySize, 53760);

    k_init<<<193, 128>>>();
    k_dft<<<dim3(8, 256), 160>>>(x);
    k_xl2<<<dim3(20, 16), 256>>>();
    k_cy <<<400, 512>>>(kern);
    k_zl <<<dim3(32, 16), 256, 105600>>>();
    k_h  <<<dim3(512, 5), 320, 96720>>>();
    k_o  <<<dim3(512, 5), 320, 53760>>>(bias, out);
}

// round 10
// speedup vs baseline: 2.3008x; 1.2161x over previous
#include <cuda_runtime.h>
#include <math.h>
#include <stdint.h>

#define PI_D 3.14159265358979323846

// B_IN=64, B_OUT=20, B_INV=20, BATCH=16, F_IN=16, F_OUT=32, N_GRID=24
// half-pair count: sum_l (l+1)(2l+1) = 5530

__constant__ int c_hoff[20]  = {0,1,7,22,50,95,161,252,372,525,715,946,1222,1547,1925,2360,2856,3417,4047,4750};
__constant__ int c_hstep[20] = {1,6,15,28,45,66,91,120,153,190,231,276,325,378,435,496,561,630,703,780};

__device__ float  g_ws2[128*400];      // [beta_b][lm]  lm = l*l + (m+l)
__device__ float2 g_cFk[24*400];       // conj(F_k) [p][lm]
__device__ float  g_dh[40*5530];       // (2l+1)*d^l_{m,n}(beta_b), m>=0 half, [b][hpair]
__device__ unsigned int g_pinfo[5530]; // (l<<12)|(m<<6)|ni
__device__ float2 g_tw[128*20];        // [a][m] e^{-2pi i a m/128}
__device__ float2 g_Xf[20*128*256];    // [m][b][zi]
__device__ float2 g_xl[16*400*16];     // [z][lm][i]
__device__ float2 g_cy[32*400*16];     // [o][lm][i]
__device__ float2 g_zl[512*5530];      // [zo][hpair]

// e^{+2pi i k/40} tables (static-index use only -> folded to immediates)
__device__ static constexpr float TWC[40] = {
 1.0f, 0.98768834f, 0.95105652f, 0.89100652f, 0.80901699f, 0.70710678f,
 0.58778525f, 0.45399050f, 0.30901699f, 0.15643447f, 0.0f, -0.15643447f,
 -0.30901699f, -0.45399050f, -0.58778525f, -0.70710678f, -0.80901699f,
 -0.89100652f, -0.95105652f, -0.98768834f, -1.0f, -0.98768834f, -0.95105652f,
 -0.89100652f, -0.80901699f, -0.70710678f, -0.58778525f, -0.45399050f,
 -0.30901699f, -0.15643447f, 0.0f, 0.15643447f, 0.30901699f, 0.45399050f,
 0.58778525f, 0.70710678f, 0.80901699f, 0.89100652f, 0.95105652f, 0.98768834f };
__device__ static constexpr float TWS[40] = {
 0.0f, 0.15643447f, 0.30901699f, 0.45399050f, 0.58778525f, 0.70710678f,
 0.80901699f, 0.89100652f, 0.95105652f, 0.98768834f, 1.0f, 0.98768834f,
 0.95105652f, 0.89100652f, 0.80901699f, 0.70710678f, 0.58778525f,
 0.45399050f, 0.30901699f, 0.15643447f, 0.0f, -0.15643447f, -0.30901699f,
 -0.45399050f, -0.58778525f, -0.70710678f, -0.80901699f, -0.89100652f,
 -0.95105652f, -0.98768834f, -1.0f, -0.98768834f, -0.95105652f, -0.89100652f,
 -0.80901699f, -0.70710678f, -0.58778525f, -0.45399050f, -0.30901699f,
 -0.15643447f };

__device__ __forceinline__ float2 cadd(float2 a, float2 b){ return make_float2(a.x+b.x, a.y+b.y); }
__device__ __forceinline__ float2 csub(float2 a, float2 b){ return make_float2(a.x-b.x, a.y-b.y); }
__device__ __forceinline__ float2 cmuli(float2 a){ return make_float2(-a.y, a.x); }      // *i
__device__ __forceinline__ float2 cmulc(float2 a, float c, float s){                     // *(c+is)
    return make_float2(a.x*c - a.y*s, a.x*s + a.y*c);
}

// ---------- fp32 Wigner-d: log-space seed + upward 3-term recurrence ----------
__device__ __forceinline__ float wseed(int m, int n, float lcb, float lsb, const float* lf) {
    int am = m < 0 ? -m : m, an = n < 0 ? -n : n;
    int l = am > an ? am : an;
    float v;
    if (am >= an) {
        float lc = 0.5f*(lf[2*l] - lf[l+n] - lf[l-n]);
        if (m >= 0) { v = expf(lc + (l+n)*lcb + (l-n)*lsb); if ((l-n)&1) v = -v; }
        else        { v = expf(lc + (l-n)*lcb + (l+n)*lsb); }
    } else {
        float lc = 0.5f*(lf[2*l] - lf[l+m] - lf[l-m]);
        if (n >= 0) { v = expf(lc + (l+m)*lcb + (l-m)*lsb); }
        else        { v = expf(lc + (l-m)*lcb + (l+m)*lsb); if ((l+m)&1) v = -v; }
    }
    return v;
}

// ---------- combined init kernel ----------
__global__ void k_init() {
    __shared__ float lf[41];
    __shared__ double sterm[64];
    __shared__ double swq;
    int t = threadIdx.x;
    if (t <= 40) lf[t] = lgammaf((float)(t + 1));
    int blk = blockIdx.x;

    if (blk < 128) {
        int b = blk;
        double beta = PI_D * (2.0*b + 1.0) / 256.0;
        if (t < 64) sterm[t] = sin((2.0*t + 1.0) * beta) / (2.0*t + 1.0);
        __syncthreads();
        if (t == 0) {
            double acc = 0.0;
            for (int k = 0; k < 64; k++) acc += sterm[k];
            swq = (2.0/64.0) * sin(beta) * acc;
        }
        __syncthreads();
        float w = (float)swq;
        float cb = (float)cos(beta*0.5), sb = (float)sin(beta*0.5);
        float cosb = (float)cos(beta);
        float lcb = logf(cb), lsb = logf(sb);
        if (t < 39) {
            int m = t - 19;
            int am = m < 0 ? -m : m;
            int l0 = am;
            float d1 = wseed(m, 0, lcb, lsb, lf), d2 = 0.0f;
            g_ws2[b*400 + l0*l0 + l0 + m] = d1 * w;
            int jstart = l0 + 1;
            if (l0 == 0) {
                d2 = d1; d1 = cosb;
                g_ws2[b*400 + 2] = d1 * w;
                jstart = 2;
            }
            for (int j = jstart; j <= 19; j++) {
                float wj  = sqrtf((float)((j*j - m*m) * (j*j)));
                float wj1 = sqrtf((float)(((j-1)*(j-1) - m*m) * ((j-1)*(j-1))));
                float d = ((2*j-1)*((float)(j*(j-1))*cosb) * d1 - (float)j*wj1*d2) / ((float)(j-1)*wj);
                g_ws2[b*400 + j*j + j + m] = d * w;
                d2 = d1; d1 = d;
            }
        }
    } else if (blk < 152) {
        int p = blk - 128;
        __syncthreads();
        double beta  = ((p >> 3) + 1) * PI_D / 24.0;
        float cb = (float)cos(beta*0.5), sb = (float)sin(beta*0.5);
        float cosb = (float)cos(beta);
        float lcb = logf(cb), lsb = logf(sb);
        if (t < 39) {
            int m = t - 19;
            int am = m < 0 ? -m : m;
            int l0 = am;
            float cph, sph;
            sincospif((float)(m * (p & 7)) * 0.25f, &sph, &cph);
            float d1 = wseed(m, 0, lcb, lsb, lf), d2 = 0.0f;
            g_cFk[p*400 + l0*l0 + l0 + m] = make_float2(d1*cph, d1*sph);
            int jstart = l0 + 1;
            if (l0 == 0) {
                d2 = d1; d1 = cosb;
                g_cFk[p*400 + 2] = make_float2(d1*cph, d1*sph);
                jstart = 2;
            }
            for (int j = jstart; j <= 19; j++) {
                float wj  = sqrtf((float)((j*j - m*m) * (j*j)));
                float wj1 = sqrtf((float)(((j-1)*(j-1) - m*m) * ((j-1)*(j-1))));
                float d = ((2*j-1)*((float)(j*(j-1))*cosb) * d1 - (float)j*wj1*d2) / ((float)(j-1)*wj);
                g_cFk[p*400 + j*j + j + m] = make_float2(d*cph, d*sph);
                d2 = d1; d1 = d;
            }
        }
    } else if (blk < 192) {
        int b = blk - 152;
        __syncthreads();
        double beta = PI_D * (2.0*b + 1.0) / 80.0;
        float cb = (float)cos(beta*0.5), sb = (float)sin(beta*0.5);
        float cosb = (float)cos(beta);
        float lcb = logf(cb), lsb = logf(sb);
        for (int p = t; p < 780; p += blockDim.x) {
            int m = p / 39, nj = p % 39, n = nj - 19;
            int an = n < 0 ? -n : n;
            int l0 = m > an ? m : an;
            float d1 = wseed(m, n, lcb, lsb, lf), d2 = 0.0f;
            g_dh[b*5530 + c_hoff[l0] + m*(2*l0+1) + n + l0] = (float)(2*l0+1) * d1;
            int jstart = l0 + 1;
            if (l0 == 0) {
                d2 = d1; d1 = cosb;
                g_dh[b*5530 + c_hoff[1] + 1] = 3.0f * d1;
                jstart = 2;
            }
            float mn = (float)(m * n);
            for (int j = jstart; j <= 19; j++) {
                float wj  = sqrtf((float)((j*j - m*m) * (j*j - n*n)));
                float wj1 = sqrtf((float)(((j-1)*(j-1) - m*m) * ((j-1)*(j-1) - n*n)));
                float d = ((2*j-1)*((float)(j*(j-1))*cosb - mn) * d1 - (float)j*wj1*d2) / ((float)(j-1)*wj);
                g_dh[b*5530 + c_hoff[j] + m*(2*j+1) + n + j] = (float)(2*j+1) * d;
                d2 = d1; d1 = d;
            }
        }
    } else {
        __syncthreads();
        for (int p = t; p < 5530; p += blockDim.x) {
            int l = 0, acc = 0;
            for (; l < 20; l++) {
                int sz = (l+1)*(2*l+1);
                if (p < acc + sz) break;
                acc += sz;
            }
            int r = p - acc, w = 2*l + 1;
            g_pinfo[p] = (unsigned)((l << 12) | ((r / w) << 6) | (r % w));
        }
        for (int idx = t; idx < 2560; idx += blockDim.x) {
            int a = idx / 20, m = idx % 20;
            float s, c;
            sincospif(-(float)(a * m) / 64.0f, &s, &c);
            g_tw[idx] = make_float2(c, s);
        }
    }
}

// ---------- K1: truncated real DFT over alpha via twiddle table ----------
__global__ void k_dft(const float* __restrict__ x) {
    __shared__ float  xs[16][130];
    __shared__ float2 tws[128*20];
    int bg = blockIdx.x, zi = blockIdx.y;
    const float* xp = x + (zi * 128 + bg * 16) * 128;
    for (int idx = threadIdx.x; idx < 2048; idx += 160)
        xs[idx >> 7][idx & 127] = xp[idx];
    for (int idx = threadIdx.x; idx < 2560; idx += 160)
        tws[idx] = g_tw[idx];
    __syncthreads();
    int bp = threadIdx.x / 20;
    int m  = threadIdx.x % 20;
    const float* r0 = xs[2*bp];
    const float* r1 = xs[2*bp + 1];
    float a0r = 0.f, a0i = 0.f, a1r = 0.f, a1i = 0.f;
    #pragma unroll 4
    for (int a = 0; a < 128; a++) {
        float2 w = tws[a*20 + m];
        float x0 = r0[a], x1 = r1[a];
        a0r += x0*w.x; a0i += x0*w.y;
        a1r += x1*w.x; a1i += x1*w.y;
    }
    int b = bg * 16 + 2*bp;
    g_Xf[(m*128 + b    )*256 + zi] = make_float2(a0r, a0i);
    g_Xf[(m*128 + b + 1)*256 + zi] = make_float2(a1r, a1i);
}

// ---------- K2: S2 analysis, tiled by (|m|, z) ----------
__global__ void k_xl2() {
    __shared__ float2 Xs[128*16];
    __shared__ float wsp[128*20];
    __shared__ float wsm[128*20];
    int ma = blockIdx.x, z = blockIdx.y;
    int nl = 20 - ma;
    int t = threadIdx.x;
    for (int idx = t; idx < 2048; idx += 256) {
        int b = idx >> 4, i = idx & 15;
        Xs[idx] = g_Xf[(ma*128 + b)*256 + z*16 + i];
    }
    for (int idx = t; idx < 128*nl; idx += 256) {
        int b = idx / nl, li = idx % nl;
        int l = ma + li;
        wsp[idx] = g_ws2[b*400 + l*l + l + ma];
        if (ma > 0) wsm[idx] = g_ws2[b*400 + l*l + l - ma];
    }
    __syncthreads();
    for (int item = t; item < nl*16; item += 256) {
        int li = item >> 4, i = item & 15;
        int l = ma + li;
        float pr = 0.f, pi = 0.f, mr = 0.f, mi = 0.f;
        for (int b = 0; b < 128; b++) {
            float2 xv = Xs[b*16 + i];
            float wp = wsp[b*nl + li];
            pr += wp * xv.x; pi += wp * xv.y;
            if (ma > 0) {
                float wm = wsm[b*nl + li];
                mr += wm * xv.x; mi -= wm * xv.y;
            }
        }
        g_xl[((size_t)z*400 + l*l + l + ma)*16 + i] = make_float2(pr, pi);
        if (ma > 0)
            g_xl[((size_t)z*400 + l*l + l - ma)*16 + i] = make_float2(mr, mi);
    }
}

// ---------- K3: cy = SCALING * conj(y) ----------
__global__ void k_cy(const float* __restrict__ kern) {
    __shared__ float2 sF[24];
    int lm = blockIdx.x;
    if (threadIdx.x < 24) sF[threadIdx.x] = g_cFk[threadIdx.x * 400 + lm];
    __syncthreads();
    int i = threadIdx.x >> 5, o = threadIdx.x & 31;
    const float* kp = kern + (i * 32 + o) * 24;
    float ar = 0.0f, ai = 0.0f;
    for (int p = 0; p < 24; p++) {
        float k = kp[p];
        ar += k * sF[p].x; ai += k * sF[p].y;
    }
    const float S = 0.00816496580927726f;
    g_cy[((size_t)o * 400 + lm) * 16 + i] = make_float2(ar * S, ai * S);
}

// ---------- K4: zl[zo][hpair] ----------
__global__ void k_zl() {
    extern __shared__ float2 sm4[];
    float2* xs = sm4;
    float2* cs = sm4 + 6400;
    int o = blockIdx.x, z = blockIdx.y;
    for (int idx = threadIdx.x; idx < 6400; idx += blockDim.x) {
        xs[idx] = g_xl[(size_t)z * 6400 + idx];
        int lm = idx >> 4, i = idx & 15;
        cs[lm * 17 + i] = g_cy[(size_t)o * 6400 + idx];
    }
    __syncthreads();
    float2* outp = g_zl + (size_t)(z * 32 + o) * 5530;
    for (int p = threadIdx.x; p < 5530; p += blockDim.x) {
        unsigned info = g_pinfo[p];
        int l = info >> 12, m = (info >> 6) & 63, ni = info & 63;
        const float2* A  = xs + (l*l + l + m) * 16;
        const float2* Bc = cs + (l*l + ni) * 17;
        float ar = 0.0f, ai = 0.0f;
        #pragma unroll
        for (int i = 0; i < 16; i++) {
            float2 a = A[i], c = Bc[i];
            ar += a.x*c.x - a.y*c.y;
            ai += a.x*c.y + a.y*c.x;
        }
        outp[p] = make_float2(ar, ai);
    }
}

// ---------- stage1 40-pt FFT partials: T[r][up] for u = 4*HH+up ----------
template<int HH>
__device__ __forceinline__ void fft40_T(const float2* __restrict__ Grow, float2 T[5][4]) {
    const float R2 = 0.70710678f;
    #pragma unroll
    for (int r = 0; r < 5; r++) {
        float2 x0=Grow[r],    x1=Grow[5+r],  x2=Grow[10+r], x3=Grow[15+r];
        float2 x4=Grow[20+r], x5=Grow[25+r], x6=Grow[30+r], x7=Grow[35+r];
        float2 a04=cadd(x0,x4), s04=csub(x0,x4);
        float2 a26=cadd(x2,x6), s26=csub(x2,x6);
        float2 E0=cadd(a04,a26), E1=cadd(s04,cmuli(s26));
        float2 E2=csub(a04,a26), E3=csub(s04,cmuli(s26));
        float2 a15=cadd(x1,x5), s15=csub(x1,x5);
        float2 a37=cadd(x3,x7), s37=csub(x3,x7);
        float2 O0=cadd(a15,a37), O1=cadd(s15,cmuli(s37));
        float2 O2=csub(a15,a37), O3=csub(s15,cmuli(s37));
        float2 w1o = make_float2(R2*(O1.x-O1.y), R2*(O1.x+O1.y));  // W8^1 * O1
        float2 w2o = cmuli(O2);                                     // W8^2 * O2
        float2 w3o = make_float2(-R2*(O3.x+O3.y), R2*(O3.x-O3.y)); // W8^3 * O3
        float2 y0, y1, y2, y3;
        if (HH == 0) { y0=cadd(E0,O0); y1=cadd(E1,w1o); y2=cadd(E2,w2o); y3=cadd(E3,w3o); }
        else         { y0=csub(E0,O0); y1=csub(E1,w1o); y2=csub(E2,w2o); y3=csub(E3,w3o); }
        T[r][0] = cmulc(y0, TWC[(r*(4*HH+0))%40], TWS[(r*(4*HH+0))%40]);
        T[r][1] = cmulc(y1, TWC[(r*(4*HH+1))%40], TWS[(r*(4*HH+1))%40]);
        T[r][2] = cmulc(y2, TWC[(r*(4*HH+2))%40], TWS[(r*(4*HH+2))%40]);
        T[r][3] = cmulc(y3, TWC[(r*(4*HH+3))%40], TWS[(r*(4*HH+3))%40]);
    }
}

// ---------- K5 fused: G-build + stage1 FFT + smem transpose + stage2 + output ----------
// smem: zs 5530 + shared G/H region 6720 (G needs 160*41=6560; H needs 160*42=6720)
__global__ void __launch_bounds__(320, 2) k_ho(const float* __restrict__ bias,
                                               float* __restrict__ out) {
    extern __shared__ float2 sm5[];
    float2* zs = sm5;          // 5530
    float2* Gs = sm5 + 5530;   // G: 160 rows x pitch 41 (6560); H: 160 cols x pitch 21 (6720)
    float2* Hs = Gs;
    int zo = blockIdx.x, bg = blockIdx.y;
    int t = threadIdx.x;
    const float2* zp = g_zl + (size_t)zo * 5530;
    for (int idx = t; idx < 5530; idx += 320) zs[idx] = zp[idx];
    __syncthreads();

    // phase 1: build G for 8 betas
    for (int e = t; e < 6400; e += 320) {
        int bloc = e / 800, rem = e - bloc*800;
        int m = rem / 40, j = rem % 40;
        int b = bg*8 + bloc;
        const float* dB = g_dh + b * 5530;
        int n = (j <= 19) ? j : j - 40;
        int an = n < 0 ? -n : n;
        int lmin = m > an ? m : an;
        int idx = c_hoff[lmin] + m*(2*lmin + 1) + (n + lmin);
        int inc = 2*m + 1;
        float gr = 0.0f, gi = 0.0f;
        #pragma unroll 2
        for (int l = lmin; l < 20; l++) {
            float d = dB[idx];
            float2 zv = zs[idx];
            gr += zv.x * d; gi += zv.y * d;
            idx += c_hstep[l] + inc;
        }
        Gs[(bloc*20 + m)*41 + j] = make_float2(gr, gi);
    }
    __syncthreads();

    // phase 2a: stage-1 FFT partials in registers (reads Gs only)
    int h = t / 160, row = t - h*160;
    int blocR = row / 20, mR = row % 20;
    float2 T[5][4];
    {
        const float2* Grow = Gs + row*41;
        if (h == 0) fft40_T<0>(Grow, T);
        else        fft40_T<1>(Grow, T);
    }
    __syncthreads();   // all Gs reads done; region becomes H

    // phase 2b: combine + write H into smem (coefficients independent of u)
    {
        float2* dsts = Hs + blocR*840 + mR;   // + (8s+u)*21
        #pragma unroll
        for (int up = 0; up < 4; up++) {
            int u = 4*h + up;
            #pragma unroll
            for (int s = 0; s < 5; s++) {
                float2 acc = T[0][up];
                #pragma unroll
                for (int r = 1; r < 5; r++)
                    acc = cadd(acc, cmulc(T[r][up], TWC[(8*r*s)%40], TWS[(8*r*s)%40]));
                dsts[(8*s + u) * 21] = acc;
            }
        }
    }
    __syncthreads();

    // phase 3: stage-2 real FFT per (b, g) column + bias + store
    {
        int bloc = t / 40, g = t - bloc*40;
        int b = bg*8 + bloc;
        const float2* col = Hs + (bloc*40 + g)*21;
        float2 hc[20];
        #pragma unroll
        for (int m = 0; m < 20; m++) hc[m] = col[m];
        hc[0].x *= 0.5f; hc[0].y *= 0.5f;
        float bv = bias[zo & 31];
        float* op = out + (size_t)zo*64000 + b*1600 + g;
        const float R2 = 0.70710678f;
        #pragma unroll
        for (int u = 0; u < 8; u++) {
            float2 B[5];
            #pragma unroll
            for (int r = 0; r < 5; r++) {
                float2 acc = hc[r];
                #pragma unroll
                for (int q = 1; q < 4; q++) {
                    int k8 = (q*u) & 7;
                    float c, s;
                    switch (k8) {
                        case 0: c=1.f;  s=0.f;  break;
                        case 1: c=R2;   s=R2;   break;
                        case 2: c=0.f;  s=1.f;  break;
                        case 3: c=-R2;  s=R2;   break;
                        case 4: c=-1.f; s=0.f;  break;
                        case 5: c=-R2;  s=-R2;  break;
                        case 6: c=0.f;  s=-1.f; break;
                        default: c=R2;  s=-R2;  break;
                    }
                    acc = cadd(acc, cmulc(hc[5*q + r], c, s));
                }
                B[r] = cmulc(acc, TWC[(r*u)%40], TWS[(r*u)%40]);
            }
            #pragma unroll
            for (int s = 0; s < 5; s++) {
                float val = B[0].x;
                #pragma unroll
                for (int r = 1; r < 5; r++)
                    val += B[r].x * TWC[(8*r*s)%40] - B[r].y * TWS[(8*r*s)%40];
                op[(8*s + u) * 40] = 2.0f*val + bv;
            }
        }
    }
}

// ---------- launch ----------
extern "C" void kernel_launch(void* const* d_in, const int* in_sizes, int n_in,
                              void* d_out, int out_size) {
    const float* x    = (const float*)d_in[0];
    const float* kern = (const float*)d_in[1];
    const float* bias = (const float*)d_in[2];
    float* out = (float*)d_out;

    cudaFuncSetAttribute(k_zl, cudaFuncAttributeMaxDynamicSharedMemorySize, 105600);
    cudaFuncSetAttribute(k_ho, cudaFuncAttributeMaxDynamicSharedMemorySize, 98000);

    k_init<<<193, 128>>>();
    k_dft<<<dim3(8, 256), 160>>>(x);
    k_xl2<<<dim3(20, 16), 256>>>();
    k_cy <<<400, 512>>>(kern);
    k_zl <<<dim3(32, 16), 256, 105600>>>();
    k_ho <<<dim3(512, 5), 320, 98000>>>(bias, out);
}

// round 11
// speedup vs baseline: 3.6133x; 1.5705x over previous
#include <cuda_runtime.h>
#include <math.h>
#include <stdint.h>

#define PI_D 3.14159265358979323846

// B_IN=64, B_OUT=20, B_INV=20, BATCH=16, F_IN=16, F_OUT=32, N_GRID=24
// half-pair count: sum_l (l+1)(2l+1) = 5530

__constant__ int c_hoff[20]  = {0,1,7,22,50,95,161,252,372,525,715,946,1222,1547,1925,2360,2856,3417,4047,4750};
__constant__ int c_hstep[20] = {1,6,15,28,45,66,91,120,153,190,231,276,325,378,435,496,561,630,703,780};

__device__ float  g_ws2[128*400];      // [beta_b][lm]  lm = l*l + (m+l)
__device__ float2 g_cFk[24*400];       // conj(F_k) [p][lm]
__device__ float  g_dh[5530*40];       // (2l+1)*d^l_{m,n}(beta_b), m>=0 half, [hpair][b] (transposed)
__device__ unsigned int g_pinfo[5530]; // (l<<12)|(m<<6)|ni
__device__ float2 g_tw[128*20];        // [a][m] e^{-2pi i a m/128}
__device__ float2 g_Xf[20*128*256];    // [m][b][zi]
__device__ float2 g_xl[16*400*16];     // [z][lm][i]
__device__ float2 g_cy[32*400*16];     // [o][lm][i]
__device__ float2 g_zl[512*5530];      // [zo][hpair]

// e^{+2pi i k/40} tables (static-index use only -> folded to immediates)
__device__ static constexpr float TWC[40] = {
 1.0f, 0.98768834f, 0.95105652f, 0.89100652f, 0.80901699f, 0.70710678f,
 0.58778525f, 0.45399050f, 0.30901699f, 0.15643447f, 0.0f, -0.15643447f,
 -0.30901699f, -0.45399050f, -0.58778525f, -0.70710678f, -0.80901699f,
 -0.89100652f, -0.95105652f, -0.98768834f, -1.0f, -0.98768834f, -0.95105652f,
 -0.89100652f, -0.80901699f, -0.70710678f, -0.58778525f, -0.45399050f,
 -0.30901699f, -0.15643447f, 0.0f, 0.15643447f, 0.30901699f, 0.45399050f,
 0.58778525f, 0.70710678f, 0.80901699f, 0.89100652f, 0.95105652f, 0.98768834f };
__device__ static constexpr float TWS[40] = {
 0.0f, 0.15643447f, 0.30901699f, 0.45399050f, 0.58778525f, 0.70710678f,
 0.80901699f, 0.89100652f, 0.95105652f, 0.98768834f, 1.0f, 0.98768834f,
 0.95105652f, 0.89100652f, 0.80901699f, 0.70710678f, 0.58778525f,
 0.45399050f, 0.30901699f, 0.15643447f, 0.0f, -0.15643447f, -0.30901699f,
 -0.45399050f, -0.58778525f, -0.70710678f, -0.80901699f, -0.89100652f,
 -0.95105652f, -0.98768834f, -1.0f, -0.98768834f, -0.95105652f, -0.89100652f,
 -0.80901699f, -0.70710678f, -0.58778525f, -0.45399050f, -0.30901699f,
 -0.15643447f };

__device__ __forceinline__ float2 cadd(float2 a, float2 b){ return make_float2(a.x+b.x, a.y+b.y); }
__device__ __forceinline__ float2 csub(float2 a, float2 b){ return make_float2(a.x-b.x, a.y-b.y); }
__device__ __forceinline__ float2 cmuli(float2 a){ return make_float2(-a.y, a.x); }      // *i
__device__ __forceinline__ float2 cmulc(float2 a, float c, float s){                     // *(c+is)
    return make_float2(a.x*c - a.y*s, a.x*s + a.y*c);
}

// ---------- fp32 Wigner-d: log-space seed + upward 3-term recurrence ----------
__device__ __forceinline__ float wseed(int m, int n, float lcb, float lsb, const float* lf) {
    int am = m < 0 ? -m : m, an = n < 0 ? -n : n;
    int l = am > an ? am : an;
    float v;
    if (am >= an) {
        float lc = 0.5f*(lf[2*l] - lf[l+n] - lf[l-n]);
        if (m >= 0) { v = expf(lc + (l+n)*lcb + (l-n)*lsb); if ((l-n)&1) v = -v; }
        else        { v = expf(lc + (l-n)*lcb + (l+n)*lsb); }
    } else {
        float lc = 0.5f*(lf[2*l] - lf[l+m] - lf[l-m]);
        if (n >= 0) { v = expf(lc + (l+m)*lcb + (l-m)*lsb); }
        else        { v = expf(lc + (l-m)*lcb + (l+m)*lsb); if ((l+m)&1) v = -v; }
    }
    return v;
}

// ---------- combined init kernel ----------
__global__ void k_init() {
    __shared__ float lf[41];
    __shared__ double sterm[64];
    __shared__ double swq;
    int t = threadIdx.x;
    if (t <= 40) lf[t] = lgammaf((float)(t + 1));
    int blk = blockIdx.x;

    if (blk < 128) {
        int b = blk;
        double beta = PI_D * (2.0*b + 1.0) / 256.0;
        if (t < 64) sterm[t] = sin((2.0*t + 1.0) * beta) / (2.0*t + 1.0);
        __syncthreads();
        if (t == 0) {
            double acc = 0.0;
            for (int k = 0; k < 64; k++) acc += sterm[k];
            swq = (2.0/64.0) * sin(beta) * acc;
        }
        __syncthreads();
        float w = (float)swq;
        float cb = (float)cos(beta*0.5), sb = (float)sin(beta*0.5);
        float cosb = (float)cos(beta);
        float lcb = logf(cb), lsb = logf(sb);
        if (t < 39) {
            int m = t - 19;
            int am = m < 0 ? -m : m;
            int l0 = am;
            float d1 = wseed(m, 0, lcb, lsb, lf), d2 = 0.0f;
            g_ws2[b*400 + l0*l0 + l0 + m] = d1 * w;
            int jstart = l0 + 1;
            if (l0 == 0) {
                d2 = d1; d1 = cosb;
                g_ws2[b*400 + 2] = d1 * w;
                jstart = 2;
            }
            for (int j = jstart; j <= 19; j++) {
                float wj  = sqrtf((float)((j*j - m*m) * (j*j)));
                float wj1 = sqrtf((float)(((j-1)*(j-1) - m*m) * ((j-1)*(j-1))));
                float d = ((2*j-1)*((float)(j*(j-1))*cosb) * d1 - (float)j*wj1*d2) / ((float)(j-1)*wj);
                g_ws2[b*400 + j*j + j + m] = d * w;
                d2 = d1; d1 = d;
            }
        }
    } else if (blk < 152) {
        int p = blk - 128;
        __syncthreads();
        double beta  = ((p >> 3) + 1) * PI_D / 24.0;
        float cb = (float)cos(beta*0.5), sb = (float)sin(beta*0.5);
        float cosb = (float)cos(beta);
        float lcb = logf(cb), lsb = logf(sb);
        if (t < 39) {
            int m = t - 19;
            int am = m < 0 ? -m : m;
            int l0 = am;
            float cph, sph;
            sincospif((float)(m * (p & 7)) * 0.25f, &sph, &cph);
            float d1 = wseed(m, 0, lcb, lsb, lf), d2 = 0.0f;
            g_cFk[p*400 + l0*l0 + l0 + m] = make_float2(d1*cph, d1*sph);
            int jstart = l0 + 1;
            if (l0 == 0) {
                d2 = d1; d1 = cosb;
                g_cFk[p*400 + 2] = make_float2(d1*cph, d1*sph);
                jstart = 2;
            }
            for (int j = jstart; j <= 19; j++) {
                float wj  = sqrtf((float)((j*j - m*m) * (j*j)));
                float wj1 = sqrtf((float)(((j-1)*(j-1) - m*m) * ((j-1)*(j-1))));
                float d = ((2*j-1)*((float)(j*(j-1))*cosb) * d1 - (float)j*wj1*d2) / ((float)(j-1)*wj);
                g_cFk[p*400 + j*j + j + m] = make_float2(d*cph, d*sph);
                d2 = d1; d1 = d;
            }
        }
    } else if (blk < 192) {
        int b = blk - 152;
        __syncthreads();
        double beta = PI_D * (2.0*b + 1.0) / 80.0;
        float cb = (float)cos(beta*0.5), sb = (float)sin(beta*0.5);
        float cosb = (float)cos(beta);
        float lcb = logf(cb), lsb = logf(sb);
        for (int p = t; p < 780; p += blockDim.x) {
            int m = p / 39, nj = p % 39, n = nj - 19;
            int an = n < 0 ? -n : n;
            int l0 = m > an ? m : an;
            float d1 = wseed(m, n, lcb, lsb, lf), d2 = 0.0f;
            g_dh[(c_hoff[l0] + m*(2*l0+1) + n + l0)*40 + b] = (float)(2*l0+1) * d1;
            int jstart = l0 + 1;
            if (l0 == 0) {
                d2 = d1; d1 = cosb;
                g_dh[(c_hoff[1] + 1)*40 + b] = 3.0f * d1;
                jstart = 2;
            }
            float mn = (float)(m * n);
            for (int j = jstart; j <= 19; j++) {
                float wj  = sqrtf((float)((j*j - m*m) * (j*j - n*n)));
                float wj1 = sqrtf((float)(((j-1)*(j-1) - m*m) * ((j-1)*(j-1) - n*n)));
                float d = ((2*j-1)*((float)(j*(j-1))*cosb - mn) * d1 - (float)j*wj1*d2) / ((float)(j-1)*wj);
                g_dh[(c_hoff[j] + m*(2*j+1) + n + j)*40 + b] = (float)(2*j+1) * d;
                d2 = d1; d1 = d;
            }
        }
    } else {
        __syncthreads();
        for (int p = t; p < 5530; p += blockDim.x) {
            int l = 0, acc = 0;
            for (; l < 20; l++) {
                int sz = (l+1)*(2*l+1);
                if (p < acc + sz) break;
                acc += sz;
            }
            int r = p - acc, w = 2*l + 1;
            g_pinfo[p] = (unsigned)((l << 12) | ((r / w) << 6) | (r % w));
        }
        for (int idx = t; idx < 2560; idx += blockDim.x) {
            int a = idx / 20, m = idx % 20;
            float s, c;
            sincospif(-(float)(a * m) / 64.0f, &s, &c);
            g_tw[idx] = make_float2(c, s);
        }
    }
}

// ---------- K1: truncated real DFT over alpha via twiddle table ----------
__global__ void k_dft(const float* __restrict__ x) {
    __shared__ float  xs[16][130];
    __shared__ float2 tws[128*20];
    int bg = blockIdx.x, zi = blockIdx.y;
    const float* xp = x + (zi * 128 + bg * 16) * 128;
    for (int idx = threadIdx.x; idx < 2048; idx += 160)
        xs[idx >> 7][idx & 127] = xp[idx];
    for (int idx = threadIdx.x; idx < 2560; idx += 160)
        tws[idx] = g_tw[idx];
    __syncthreads();
    int bp = threadIdx.x / 20;
    int m  = threadIdx.x % 20;
    const float* r0 = xs[2*bp];
    const float* r1 = xs[2*bp + 1];
    float a0r = 0.f, a0i = 0.f, a1r = 0.f, a1i = 0.f;
    #pragma unroll 4
    for (int a = 0; a < 128; a++) {
        float2 w = tws[a*20 + m];
        float x0 = r0[a], x1 = r1[a];
        a0r += x0*w.x; a0i += x0*w.y;
        a1r += x1*w.x; a1i += x1*w.y;
    }
    int b = bg * 16 + 2*bp;
    g_Xf[(m*128 + b    )*256 + zi] = make_float2(a0r, a0i);
    g_Xf[(m*128 + b + 1)*256 + zi] = make_float2(a1r, a1i);
}

// ---------- K2: S2 analysis, tiled by (|m|, z) ----------
__global__ void k_xl2() {
    __shared__ float2 Xs[128*16];
    __shared__ float wsp[128*20];
    __shared__ float wsm[128*20];
    int ma = blockIdx.x, z = blockIdx.y;
    int nl = 20 - ma;
    int t = threadIdx.x;
    for (int idx = t; idx < 2048; idx += 256) {
        int b = idx >> 4, i = idx & 15;
        Xs[idx] = g_Xf[(ma*128 + b)*256 + z*16 + i];
    }
    for (int idx = t; idx < 128*nl; idx += 256) {
        int b = idx / nl, li = idx % nl;
        int l = ma + li;
        wsp[idx] = g_ws2[b*400 + l*l + l + ma];
        if (ma > 0) wsm[idx] = g_ws2[b*400 + l*l + l - ma];
    }
    __syncthreads();
    for (int item = t; item < nl*16; item += 256) {
        int li = item >> 4, i = item & 15;
        int l = ma + li;
        float pr = 0.f, pi = 0.f, mr = 0.f, mi = 0.f;
        for (int b = 0; b < 128; b++) {
            float2 xv = Xs[b*16 + i];
            float wp = wsp[b*nl + li];
            pr += wp * xv.x; pi += wp * xv.y;
            if (ma > 0) {
                float wm = wsm[b*nl + li];
                mr += wm * xv.x; mi -= wm * xv.y;
            }
        }
        g_xl[((size_t)z*400 + l*l + l + ma)*16 + i] = make_float2(pr, pi);
        if (ma > 0)
            g_xl[((size_t)z*400 + l*l + l - ma)*16 + i] = make_float2(mr, mi);
    }
}

// ---------- K3: cy = SCALING * conj(y) ----------
__global__ void k_cy(const float* __restrict__ kern) {
    __shared__ float2 sF[24];
    int lm = blockIdx.x;
    if (threadIdx.x < 24) sF[threadIdx.x] = g_cFk[threadIdx.x * 400 + lm];
    __syncthreads();
    int i = threadIdx.x >> 5, o = threadIdx.x & 31;
    const float* kp = kern + (i * 32 + o) * 24;
    float ar = 0.0f, ai = 0.0f;
    for (int p = 0; p < 24; p++) {
        float k = kp[p];
        ar += k * sF[p].x; ai += k * sF[p].y;
    }
    const float S = 0.00816496580927726f;
    g_cy[((size_t)o * 400 + lm) * 16 + i] = make_float2(ar * S, ai * S);
}

// ---------- K4: zl[zo][hpair] ----------
__global__ void k_zl() {
    extern __shared__ float2 sm4[];
    float2* xs = sm4;
    float2* cs = sm4 + 6400;
    int o = blockIdx.x, z = blockIdx.y;
    for (int idx = threadIdx.x; idx < 6400; idx += blockDim.x) {
        xs[idx] = g_xl[(size_t)z * 6400 + idx];
        int lm = idx >> 4, i = idx & 15;
        cs[lm * 17 + i] = g_cy[(size_t)o * 6400 + idx];
    }
    __syncthreads();
    float2* outp = g_zl + (size_t)(z * 32 + o) * 5530;
    for (int p = threadIdx.x; p < 5530; p += blockDim.x) {
        unsigned info = g_pinfo[p];
        int l = info >> 12, m = (info >> 6) & 63, ni = info & 63;
        const float2* A  = xs + (l*l + l + m) * 16;
        const float2* Bc = cs + (l*l + ni) * 17;
        float ar = 0.0f, ai = 0.0f;
        #pragma unroll
        for (int i = 0; i < 16; i++) {
            float2 a = A[i], c = Bc[i];
            ar += a.x*c.x - a.y*c.y;
            ai += a.x*c.y + a.y*c.x;
        }
        outp[p] = make_float2(ar, ai);
    }
}

// ---------- stage1 40-pt FFT partials: T[r][up] for u = 4*HH+up ----------
template<int HH>
__device__ __forceinline__ void fft40_T(const float2* __restrict__ Grow, float2 T[5][4]) {
    const float R2 = 0.70710678f;
    #pragma unroll
    for (int r = 0; r < 5; r++) {
        float2 x0=Grow[r],    x1=Grow[5+r],  x2=Grow[10+r], x3=Grow[15+r];
        float2 x4=Grow[20+r], x5=Grow[25+r], x6=Grow[30+r], x7=Grow[35+r];
        float2 a04=cadd(x0,x4), s04=csub(x0,x4);
        float2 a26=cadd(x2,x6), s26=csub(x2,x6);
        float2 E0=cadd(a04,a26), E1=cadd(s04,cmuli(s26));
        float2 E2=csub(a04,a26), E3=csub(s04,cmuli(s26));
        float2 a15=cadd(x1,x5), s15=csub(x1,x5);
        float2 a37=cadd(x3,x7), s37=csub(x3,x7);
        float2 O0=cadd(a15,a37), O1=cadd(s15,cmuli(s37));
        float2 O2=csub(a15,a37), O3=csub(s15,cmuli(s37));
        float2 w1o = make_float2(R2*(O1.x-O1.y), R2*(O1.x+O1.y));  // W8^1 * O1
        float2 w2o = cmuli(O2);                                     // W8^2 * O2
        float2 w3o = make_float2(-R2*(O3.x+O3.y), R2*(O3.x-O3.y)); // W8^3 * O3
        float2 y0, y1, y2, y3;
        if (HH == 0) { y0=cadd(E0,O0); y1=cadd(E1,w1o); y2=cadd(E2,w2o); y3=cadd(E3,w3o); }
        else         { y0=csub(E0,O0); y1=csub(E1,w1o); y2=csub(E2,w2o); y3=csub(E3,w3o); }
        T[r][0] = cmulc(y0, TWC[(r*(4*HH+0))%40], TWS[(r*(4*HH+0))%40]);
        T[r][1] = cmulc(y1, TWC[(r*(4*HH+1))%40], TWS[(r*(4*HH+1))%40]);
        T[r][2] = cmulc(y2, TWC[(r*(4*HH+2))%40], TWS[(r*(4*HH+2))%40]);
        T[r][3] = cmulc(y3, TWC[(r*(4*HH+3))%40], TWS[(r*(4*HH+3))%40]);
    }
}

// ---------- K5 fused: register-blocked G-build + stage1 FFT + stage2 + output ----------
// smem: G/H region only (G: 160 x pitch 41 = 6560; H: 160 x pitch 21 laid as bloc*840 -> 6720)
__global__ void __launch_bounds__(320, 3) k_ho(const float* __restrict__ bias,
                                               float* __restrict__ out) {
    extern __shared__ float2 sm5[];
    float2* Gs = sm5;
    float2* Hs = sm5;
    int zo = blockIdx.x, bg = blockIdx.y;
    int t = threadIdx.x;

    // phase 1: build G for 8 betas at once (register-blocked over beta)
    const float2* zrow = g_zl + (size_t)zo * 5530;
    for (int e = t; e < 800; e += 320) {
        int m = e / 40, j = e % 40;
        int n = (j <= 19) ? j : j - 40;
        int an = n < 0 ? -n : n;
        int lmin = m > an ? m : an;
        int idx = c_hoff[lmin] + m*(2*lmin + 1) + (n + lmin);
        int inc = 2*m + 1;
        float gr0=0.f,gi0=0.f,gr1=0.f,gi1=0.f,gr2=0.f,gi2=0.f,gr3=0.f,gi3=0.f;
        float gr4=0.f,gi4=0.f,gr5=0.f,gi5=0.f,gr6=0.f,gi6=0.f,gr7=0.f,gi7=0.f;
        for (int l = lmin; l < 20; l++) {
            float2 zv = __ldg(zrow + idx);
            const float4* dp = (const float4*)(g_dh + (size_t)idx*40 + bg*8);
            float4 d0 = __ldg(dp), d1 = __ldg(dp + 1);
            gr0 += zv.x*d0.x; gi0 += zv.y*d0.x;
            gr1 += zv.x*d0.y; gi1 += zv.y*d0.y;
            gr2 += zv.x*d0.z; gi2 += zv.y*d0.z;
            gr3 += zv.x*d0.w; gi3 += zv.y*d0.w;
            gr4 += zv.x*d1.x; gi4 += zv.y*d1.x;
            gr5 += zv.x*d1.y; gi5 += zv.y*d1.y;
            gr6 += zv.x*d1.z; gi6 += zv.y*d1.z;
            gr7 += zv.x*d1.w; gi7 += zv.y*d1.w;
            idx += c_hstep[l] + inc;
        }
        int base = m*41 + j;
        Gs[base        ] = make_float2(gr0, gi0);
        Gs[base +  820 ] = make_float2(gr1, gi1);
        Gs[base + 1640 ] = make_float2(gr2, gi2);
        Gs[base + 2460 ] = make_float2(gr3, gi3);
        Gs[base + 3280 ] = make_float2(gr4, gi4);
        Gs[base + 4100 ] = make_float2(gr5, gi5);
        Gs[base + 4920 ] = make_float2(gr6, gi6);
        Gs[base + 5740 ] = make_float2(gr7, gi7);
    }
    __syncthreads();

    // phase 2a: stage-1 FFT partials in registers (reads Gs only)
    int h = t / 160, row = t - h*160;
    int blocR = row / 20, mR = row % 20;
    float2 T[5][4];
    {
        const float2* Grow = Gs + row*41;   // row = bloc*20 + m -> offset bloc*820 + m*41
        if (h == 0) fft40_T<0>(Grow, T);
        else        fft40_T<1>(Grow, T);
    }
    __syncthreads();   // all Gs reads done; region becomes H

    // phase 2b: combine + write H into smem (coefficients independent of u)
    {
        float2* dsts = Hs + blocR*840 + mR;   // + (8s+u)*21
        #pragma unroll
        for (int up = 0; up < 4; up++) {
            int u = 4*h + up;
            #pragma unroll
            for (int s = 0; s < 5; s++) {
                float2 acc = T[0][up];
                #pragma unroll
                for (int r = 1; r < 5; r++)
                    acc = cadd(acc, cmulc(T[r][up], TWC[(8*r*s)%40], TWS[(8*r*s)%40]));
                dsts[(8*s + u) * 21] = acc;
            }
        }
    }
    __syncthreads();

    // phase 3: stage-2 real FFT per (b, g) column + bias + store
    {
        int bloc = t / 40, g = t - bloc*40;
        int b = bg*8 + bloc;
        const float2* col = Hs + (bloc*40 + g)*21;
        float2 hc[20];
        #pragma unroll
        for (int m = 0; m < 20; m++) hc[m] = col[m];
        hc[0].x *= 0.5f; hc[0].y *= 0.5f;
        float bv = bias[zo & 31];
        float* op = out + (size_t)zo*64000 + b*1600 + g;
        const float R2 = 0.70710678f;
        #pragma unroll
        for (int u = 0; u < 8; u++) {
            float2 B[5];
            #pragma unroll
            for (int r = 0; r < 5; r++) {
                float2 acc = hc[r];
                #pragma unroll
                for (int q = 1; q < 4; q++) {
                    int k8 = (q*u) & 7;
                    float c, s;
                    switch (k8) {
                        case 0: c=1.f;  s=0.f;  break;
                        case 1: c=R2;   s=R2;   break;
                        case 2: c=0.f;  s=1.f;  break;
                        case 3: c=-R2;  s=R2;   break;
                        case 4: c=-1.f; s=0.f;  break;
                        case 5: c=-R2;  s=-R2;  break;
                        case 6: c=0.f;  s=-1.f; break;
                        default: c=R2;  s=-R2;  break;
                    }
                    acc = cadd(acc, cmulc(hc[5*q + r], c, s));
                }
                B[r] = cmulc(acc, TWC[(r*u)%40], TWS[(r*u)%40]);
            }
            #pragma unroll
            for (int s = 0; s < 5; s++) {
                float val = B[0].x;
                #pragma unroll
                for (int r = 1; r < 5; r++)
                    val += B[r].x * TWC[(8*r*s)%40] - B[r].y * TWS[(8*r*s)%40];
                op[(8*s + u) * 40] = 2.0f*val + bv;
            }
        }
    }
}

// ---------- launch ----------
extern "C" void kernel_launch(void* const* d_in, const int* in_sizes, int n_in,
                              void* d_out, int out_size) {
    const float* x    = (const float*)d_in[0];
    const float* kern = (const float*)d_in[1];
    const float* bias = (const float*)d_in[2];
    float* out = (float*)d_out;

    cudaFuncSetAttribute(k_zl, cudaFuncAttributeMaxDynamicSharedMemorySize, 105600);
    cudaFuncSetAttribute(k_ho, cudaFuncAttributeMaxDynamicSharedMemorySize, 53760);

    k_init<<<193, 128>>>();
    k_dft<<<dim3(8, 256), 160>>>(x);
    k_xl2<<<dim3(20, 16), 256>>>();
    k_cy <<<400, 512>>>(kern);
    k_zl <<<dim3(32, 16), 256, 105600>>>();
    k_ho <<<dim3(512, 5), 320, 53760>>>(bias, out);
}

// round 12
// speedup vs baseline: 3.9532x; 1.0941x over previous
#include <cuda_runtime.h>
#include <math.h>
#include <stdint.h>

#define PI_D 3.14159265358979323846

// B_IN=64, B_OUT=20, B_INV=20, BATCH=16, F_IN=16, F_OUT=32, N_GRID=24
// half-pair count: sum_l (l+1)(2l+1) = 5530

__constant__ int c_hoff[20]  = {0,1,7,22,50,95,161,252,372,525,715,946,1222,1547,1925,2360,2856,3417,4047,4750};
__constant__ int c_hstep[20] = {1,6,15,28,45,66,91,120,153,190,231,276,325,378,435,496,561,630,703,780};

__device__ float  g_ws2[128*400];      // [beta_b][lm]  lm = l*l + (m+l)
__device__ float2 g_cFk[24*400];       // conj(F_k) [p][lm]
__device__ float4 g_dhA[5*5530];       // (2l+1)*d, betas bg*8+0..3, [bg][hpair]
__device__ float4 g_dhB[5*5530];       // betas bg*8+4..7
__device__ unsigned int g_pinfo[5530]; // (l<<12)|(m<<6)|ni
__device__ float2 g_tw[128*20];        // [a][m] e^{-2pi i a m/128}
__device__ float2 g_Xf[20*128*256];    // [m][b][zi]
__device__ float2 g_xl[16*400*16];     // [z][lm][i]
__device__ float2 g_cy[32*400*16];     // [o][lm][i]
__device__ float2 g_zl[512*5530];      // [zo][hpair]

// e^{+2pi i k/40} tables (static-index use only -> folded to immediates)
__device__ static constexpr float TWC[40] = {
 1.0f, 0.98768834f, 0.95105652f, 0.89100652f, 0.80901699f, 0.70710678f,
 0.58778525f, 0.45399050f, 0.30901699f, 0.15643447f, 0.0f, -0.15643447f,
 -0.30901699f, -0.45399050f, -0.58778525f, -0.70710678f, -0.80901699f,
 -0.89100652f, -0.95105652f, -0.98768834f, -1.0f, -0.98768834f, -0.95105652f,
 -0.89100652f, -0.80901699f, -0.70710678f, -0.58778525f, -0.45399050f,
 -0.30901699f, -0.15643447f, 0.0f, 0.15643447f, 0.30901699f, 0.45399050f,
 0.58778525f, 0.70710678f, 0.80901699f, 0.89100652f, 0.95105652f, 0.98768834f };
__device__ static constexpr float TWS[40] = {
 0.0f, 0.15643447f, 0.30901699f, 0.45399050f, 0.58778525f, 0.70710678f,
 0.80901699f, 0.89100652f, 0.95105652f, 0.98768834f, 1.0f, 0.98768834f,
 0.95105652f, 0.89100652f, 0.80901699f, 0.70710678f, 0.58778525f,
 0.45399050f, 0.30901699f, 0.15643447f, 0.0f, -0.15643447f, -0.30901699f,
 -0.45399050f, -0.58778525f, -0.70710678f, -0.80901699f, -0.89100652f,
 -0.95105652f, -0.98768834f, -1.0f, -0.98768834f, -0.95105652f, -0.89100652f,
 -0.80901699f, -0.70710678f, -0.58778525f, -0.45399050f, -0.30901699f,
 -0.15643447f };

__device__ __forceinline__ float2 cadd(float2 a, float2 b){ return make_float2(a.x+b.x, a.y+b.y); }
__device__ __forceinline__ float2 csub(float2 a, float2 b){ return make_float2(a.x-b.x, a.y-b.y); }
__device__ __forceinline__ float2 cmuli(float2 a){ return make_float2(-a.y, a.x); }      // *i
__device__ __forceinline__ float2 cmulc(float2 a, float c, float s){                     // *(c+is)
    return make_float2(a.x*c - a.y*s, a.x*s + a.y*c);
}

// store one (beta, hpair) value into the split coalesced d-tables
__device__ __forceinline__ void store_d(int b, int hidx, float v) {
    int bb = b & 7, bgi = b >> 3;
    if (bb < 4) ((float*)&g_dhA[bgi*5530 + hidx])[bb] = v;
    else        ((float*)&g_dhB[bgi*5530 + hidx])[bb - 4] = v;
}

// ---------- fp32 Wigner-d: log-space seed + upward 3-term recurrence ----------
__device__ __forceinline__ float wseed(int m, int n, float lcb, float lsb, const float* lf) {
    int am = m < 0 ? -m : m, an = n < 0 ? -n : n;
    int l = am > an ? am : an;
    float v;
    if (am >= an) {
        float lc = 0.5f*(lf[2*l] - lf[l+n] - lf[l-n]);
        if (m >= 0) { v = expf(lc + (l+n)*lcb + (l-n)*lsb); if ((l-n)&1) v = -v; }
        else        { v = expf(lc + (l-n)*lcb + (l+n)*lsb); }
    } else {
        float lc = 0.5f*(lf[2*l] - lf[l+m] - lf[l-m]);
        if (n >= 0) { v = expf(lc + (l+m)*lcb + (l-m)*lsb); }
        else        { v = expf(lc + (l-m)*lcb + (l+m)*lsb); if ((l+m)&1) v = -v; }
    }
    return v;
}

// ---------- combined init kernel ----------
__global__ void k_init() {
    __shared__ float lf[41];
    __shared__ double sterm[64];
    __shared__ double swq;
    int t = threadIdx.x;
    if (t <= 40) lf[t] = lgammaf((float)(t + 1));
    int blk = blockIdx.x;

    if (blk < 128) {
        int b = blk;
        double beta = PI_D * (2.0*b + 1.0) / 256.0;
        if (t < 64) sterm[t] = sin((2.0*t + 1.0) * beta) / (2.0*t + 1.0);
        __syncthreads();
        if (t == 0) {
            double acc = 0.0;
            for (int k = 0; k < 64; k++) acc += sterm[k];
            swq = (2.0/64.0) * sin(beta) * acc;
        }
        __syncthreads();
        float w = (float)swq;
        float cb = (float)cos(beta*0.5), sb = (float)sin(beta*0.5);
        float cosb = (float)cos(beta);
        float lcb = logf(cb), lsb = logf(sb);
        if (t < 39) {
            int m = t - 19;
            int am = m < 0 ? -m : m;
            int l0 = am;
            float d1 = wseed(m, 0, lcb, lsb, lf), d2 = 0.0f;
            g_ws2[b*400 + l0*l0 + l0 + m] = d1 * w;
            int jstart = l0 + 1;
            if (l0 == 0) {
                d2 = d1; d1 = cosb;
                g_ws2[b*400 + 2] = d1 * w;
                jstart = 2;
            }
            for (int j = jstart; j <= 19; j++) {
                float wj  = sqrtf((float)((j*j - m*m) * (j*j)));
                float wj1 = sqrtf((float)(((j-1)*(j-1) - m*m) * ((j-1)*(j-1))));
                float d = ((2*j-1)*((float)(j*(j-1))*cosb) * d1 - (float)j*wj1*d2) / ((float)(j-1)*wj);
                g_ws2[b*400 + j*j + j + m] = d * w;
                d2 = d1; d1 = d;
            }
        }
    } else if (blk < 152) {
        int p = blk - 128;
        __syncthreads();
        double beta  = ((p >> 3) + 1) * PI_D / 24.0;
        float cb = (float)cos(beta*0.5), sb = (float)sin(beta*0.5);
        float cosb = (float)cos(beta);
        float lcb = logf(cb), lsb = logf(sb);
        if (t < 39) {
            int m = t - 19;
            int am = m < 0 ? -m : m;
            int l0 = am;
            float cph, sph;
            sincospif((float)(m * (p & 7)) * 0.25f, &sph, &cph);
            float d1 = wseed(m, 0, lcb, lsb, lf), d2 = 0.0f;
            g_cFk[p*400 + l0*l0 + l0 + m] = make_float2(d1*cph, d1*sph);
            int jstart = l0 + 1;
            if (l0 == 0) {
                d2 = d1; d1 = cosb;
                g_cFk[p*400 + 2] = make_float2(d1*cph, d1*sph);
                jstart = 2;
            }
            for (int j = jstart; j <= 19; j++) {
                float wj  = sqrtf((float)((j*j - m*m) * (j*j)));
                float wj1 = sqrtf((float)(((j-1)*(j-1) - m*m) * ((j-1)*(j-1))));
                float d = ((2*j-1)*((float)(j*(j-1))*cosb) * d1 - (float)j*wj1*d2) / ((float)(j-1)*wj);
                g_cFk[p*400 + j*j + j + m] = make_float2(d*cph, d*sph);
                d2 = d1; d1 = d;
            }
        }
    } else if (blk < 192) {
        int b = blk - 152;
        __syncthreads();
        double beta = PI_D * (2.0*b + 1.0) / 80.0;
        float cb = (float)cos(beta*0.5), sb = (float)sin(beta*0.5);
        float cosb = (float)cos(beta);
        float lcb = logf(cb), lsb = logf(sb);
        for (int p = t; p < 780; p += blockDim.x) {
            int m = p / 39, nj = p % 39, n = nj - 19;
            int an = n < 0 ? -n : n;
            int l0 = m > an ? m : an;
            float d1 = wseed(m, n, lcb, lsb, lf), d2 = 0.0f;
            store_d(b, c_hoff[l0] + m*(2*l0+1) + n + l0, (float)(2*l0+1) * d1);
            int jstart = l0 + 1;
            if (l0 == 0) {
                d2 = d1; d1 = cosb;
                store_d(b, c_hoff[1] + 1, 3.0f * d1);
                jstart = 2;
            }
            float mn = (float)(m * n);
            for (int j = jstart; j <= 19; j++) {
                float wj  = sqrtf((float)((j*j - m*m) * (j*j - n*n)));
                float wj1 = sqrtf((float)(((j-1)*(j-1) - m*m) * ((j-1)*(j-1) - n*n)));
                float d = ((2*j-1)*((float)(j*(j-1))*cosb - mn) * d1 - (float)j*wj1*d2) / ((float)(j-1)*wj);
                store_d(b, c_hoff[j] + m*(2*j+1) + n + j, (float)(2*j+1) * d);
                d2 = d1; d1 = d;
            }
        }
    } else {
        __syncthreads();
        for (int p = t; p < 5530; p += blockDim.x) {
            int l = 0, acc = 0;
            for (; l < 20; l++) {
                int sz = (l+1)*(2*l+1);
                if (p < acc + sz) break;
                acc += sz;
            }
            int r = p - acc, w = 2*l + 1;
            g_pinfo[p] = (unsigned)((l << 12) | ((r / w) << 6) | (r % w));
        }
        for (int idx = t; idx < 2560; idx += blockDim.x) {
            int a = idx / 20, m = idx % 20;
            float s, c;
            sincospif(-(float)(a * m) / 64.0f, &s, &c);
            g_tw[idx] = make_float2(c, s);
        }
    }
}

// ---------- K1: truncated real DFT over alpha via twiddle table ----------
__global__ void k_dft(const float* __restrict__ x) {
    __shared__ float  xs[16][130];
    __shared__ float2 tws[128*20];
    int bg = blockIdx.x, zi = blockIdx.y;
    const float* xp = x + (zi * 128 + bg * 16) * 128;
    for (int idx = threadIdx.x; idx < 2048; idx += 160)
        xs[idx >> 7][idx & 127] = xp[idx];
    for (int idx = threadIdx.x; idx < 2560; idx += 160)
        tws[idx] = g_tw[idx];
    __syncthreads();
    int bp = threadIdx.x / 20;
    int m  = threadIdx.x % 20;
    const float* r0 = xs[2*bp];
    const float* r1 = xs[2*bp + 1];
    float a0r = 0.f, a0i = 0.f, a1r = 0.f, a1i = 0.f;
    #pragma unroll 4
    for (int a = 0; a < 128; a++) {
        float2 w = tws[a*20 + m];
        float x0 = r0[a], x1 = r1[a];
        a0r += x0*w.x; a0i += x0*w.y;
        a1r += x1*w.x; a1i += x1*w.y;
    }
    int b = bg * 16 + 2*bp;
    g_Xf[(m*128 + b    )*256 + zi] = make_float2(a0r, a0i);
    g_Xf[(m*128 + b + 1)*256 + zi] = make_float2(a1r, a1i);
}

// ---------- K2: S2 analysis tiled by (|m|, z), with k_cy work fused as extra blocks ----------
// grid (45, 16): x<20 -> xl2 path (ma=x, z=y); x>=20 -> cy path (lm = (x-20)*16 + y)
__global__ void k_xl2cy(const float* __restrict__ kern) {
    __shared__ float2 Xs[128*16];
    __shared__ float wsp[128*20];
    __shared__ float wsm[128*20];
    __shared__ float2 sF[24];
    int t = threadIdx.x;
    if (blockIdx.x >= 20) {
        // ---- cy path: cy[o][lm][i] = SCALING * conj(y), one block per lm ----
        int lm = (blockIdx.x - 20) * 16 + blockIdx.y;
        if (t < 24) sF[t] = g_cFk[t * 400 + lm];
        __syncthreads();
        int i = t >> 5, o = t & 31;
        const float* kp = kern + (i * 32 + o) * 24;
        float ar = 0.0f, ai = 0.0f;
        for (int p = 0; p < 24; p++) {
            float k = kp[p];
            ar += k * sF[p].x; ai += k * sF[p].y;
        }
        const float S = 0.00816496580927726f;
        g_cy[((size_t)o * 400 + lm) * 16 + i] = make_float2(ar * S, ai * S);
        return;
    }
    // ---- xl2 path ----
    int ma = blockIdx.x, z = blockIdx.y;
    int nl = 20 - ma;
    for (int idx = t; idx < 2048; idx += 512) {
        int b = idx >> 4, i = idx & 15;
        Xs[idx] = g_Xf[(ma*128 + b)*256 + z*16 + i];
    }
    for (int idx = t; idx < 128*nl; idx += 512) {
        int b = idx / nl, li = idx % nl;
        int l = ma + li;
        wsp[idx] = g_ws2[b*400 + l*l + l + ma];
        if (ma > 0) wsm[idx] = g_ws2[b*400 + l*l + l - ma];
    }
    __syncthreads();
    for (int item = t; item < nl*16; item += 512) {
        int li = item >> 4, i = item & 15;
        int l = ma + li;
        float pr = 0.f, pi = 0.f, mr = 0.f, mi = 0.f;
        for (int b = 0; b < 128; b++) {
            float2 xv = Xs[b*16 + i];
            float wp = wsp[b*nl + li];
            pr += wp * xv.x; pi += wp * xv.y;
            if (ma > 0) {
                float wm = wsm[b*nl + li];
                mr += wm * xv.x; mi -= wm * xv.y;
            }
        }
        g_xl[((size_t)z*400 + l*l + l + ma)*16 + i] = make_float2(pr, pi);
        if (ma > 0)
            g_xl[((size_t)z*400 + l*l + l - ma)*16 + i] = make_float2(mr, mi);
    }
}

// ---------- K4: zl[zo][hpair] ----------
__global__ void k_zl() {
    extern __shared__ float2 sm4[];
    float2* xs = sm4;
    float2* cs = sm4 + 6400;
    int o = blockIdx.x, z = blockIdx.y;
    for (int idx = threadIdx.x; idx < 6400; idx += blockDim.x) {
        xs[idx] = g_xl[(size_t)z * 6400 + idx];
        int lm = idx >> 4, i = idx & 15;
        cs[lm * 17 + i] = g_cy[(size_t)o * 6400 + idx];
    }
    __syncthreads();
    float2* outp = g_zl + (size_t)(z * 32 + o) * 5530;
    for (int p = threadIdx.x; p < 5530; p += blockDim.x) {
        unsigned info = g_pinfo[p];
        int l = info >> 12, m = (info >> 6) & 63, ni = info & 63;
        const float2* A  = xs + (l*l + l + m) * 16;
        const float2* Bc = cs + (l*l + ni) * 17;
        float ar = 0.0f, ai = 0.0f;
        #pragma unroll
        for (int i = 0; i < 16; i++) {
            float2 a = A[i], c = Bc[i];
            ar += a.x*c.x - a.y*c.y;
            ai += a.x*c.y + a.y*c.x;
        }
        outp[p] = make_float2(ar, ai);
    }
}

// ---------- stage1 40-pt FFT partials: T[r][up] for u = 4*HH+up ----------
template<int HH>
__device__ __forceinline__ void fft40_T(const float2* __restrict__ Grow, float2 T[5][4]) {
    const float R2 = 0.70710678f;
    #pragma unroll
    for (int r = 0; r < 5; r++) {
        float2 x0=Grow[r],    x1=Grow[5+r],  x2=Grow[10+r], x3=Grow[15+r];
        float2 x4=Grow[20+r], x5=Grow[25+r], x6=Grow[30+r], x7=Grow[35+r];
        float2 a04=cadd(x0,x4), s04=csub(x0,x4);
        float2 a26=cadd(x2,x6), s26=csub(x2,x6);
        float2 E0=cadd(a04,a26), E1=cadd(s04,cmuli(s26));
        float2 E2=csub(a04,a26), E3=csub(s04,cmuli(s26));
        float2 a15=cadd(x1,x5), s15=csub(x1,x5);
        float2 a37=cadd(x3,x7), s37=csub(x3,x7);
        float2 O0=cadd(a15,a37), O1=cadd(s15,cmuli(s37));
        float2 O2=csub(a15,a37), O3=csub(s15,cmuli(s37));
        float2 w1o = make_float2(R2*(O1.x-O1.y), R2*(O1.x+O1.y));  // W8^1 * O1
        float2 w2o = cmuli(O2);                                     // W8^2 * O2
        float2 w3o = make_float2(-R2*(O3.x+O3.y), R2*(O3.x-O3.y)); // W8^3 * O3
        float2 y0, y1, y2, y3;
        if (HH == 0) { y0=cadd(E0,O0); y1=cadd(E1,w1o); y2=cadd(E2,w2o); y3=cadd(E3,w3o); }
        else         { y0=csub(E0,O0); y1=csub(E1,w1o); y2=csub(E2,w2o); y3=csub(E3,w3o); }
        T[r][0] = cmulc(y0, TWC[(r*(4*HH+0))%40], TWS[(r*(4*HH+0))%40]);
        T[r][1] = cmulc(y1, TWC[(r*(4*HH+1))%40], TWS[(r*(4*HH+1))%40]);
        T[r][2] = cmulc(y2, TWC[(r*(4*HH+2))%40], TWS[(r*(4*HH+2))%40]);
        T[r][3] = cmulc(y3, TWC[(r*(4*HH+3))%40], TWS[(r*(4*HH+3))%40]);
    }
}

// ---------- K5 fused: register-blocked G-build + stage1 FFT + stage2 + output ----------
__global__ void __launch_bounds__(320, 3) k_ho(const float* __restrict__ bias,
                                               float* __restrict__ out) {
    extern __shared__ float2 sm5[];
    float2* Gs = sm5;
    float2* Hs = sm5;
    int zo = blockIdx.x, bg = blockIdx.y;
    int t = threadIdx.x;

    // phase 1: build G for 8 betas at once (register-blocked over beta, coalesced d)
    const float2* zrow = g_zl + (size_t)zo * 5530;
    const float4* dA = g_dhA + bg * 5530;
    const float4* dB = g_dhB + bg * 5530;
    for (int e = t; e < 800; e += 320) {
        int m = e / 40, j = e % 40;
        int n = (j <= 19) ? j : j - 40;
        int an = n < 0 ? -n : n;
        int lmin = m > an ? m : an;
        int idx = c_hoff[lmin] + m*(2*lmin + 1) + (n + lmin);
        int inc = 2*m + 1;
        float gr0=0.f,gi0=0.f,gr1=0.f,gi1=0.f,gr2=0.f,gi2=0.f,gr3=0.f,gi3=0.f;
        float gr4=0.f,gi4=0.f,gr5=0.f,gi5=0.f,gr6=0.f,gi6=0.f,gr7=0.f,gi7=0.f;
        for (int l = lmin; l < 20; l++) {
            float2 zv = __ldg(zrow + idx);
            float4 d0 = __ldg(dA + idx);
            float4 d1 = __ldg(dB + idx);
            gr0 += zv.x*d0.x; gi0 += zv.y*d0.x;
            gr1 += zv.x*d0.y; gi1 += zv.y*d0.y;
            gr2 += zv.x*d0.z; gi2 += zv.y*d0.z;
            gr3 += zv.x*d0.w; gi3 += zv.y*d0.w;
            gr4 += zv.x*d1.x; gi4 += zv.y*d1.x;
            gr5 += zv.x*d1.y; gi5 += zv.y*d1.y;
            gr6 += zv.x*d1.z; gi6 += zv.y*d1.z;
            gr7 += zv.x*d1.w; gi7 += zv.y*d1.w;
            idx += c_hstep[l] + inc;
        }
        int base = m*41 + j;
        Gs[base        ] = make_float2(gr0, gi0);
        Gs[base +  820 ] = make_float2(gr1, gi1);
        Gs[base + 1640 ] = make_float2(gr2, gi2);
        Gs[base + 2460 ] = make_float2(gr3, gi3);
        Gs[base + 3280 ] = make_float2(gr4, gi4);
        Gs[base + 4100 ] = make_float2(gr5, gi5);
        Gs[base + 4920 ] = make_float2(gr6, gi6);
        Gs[base + 5740 ] = make_float2(gr7, gi7);
    }
    __syncthreads();

    // phase 2a: stage-1 FFT partials in registers (reads Gs only)
    int h = t / 160, row = t - h*160;
    int blocR = row / 20, mR = row % 20;
    float2 T[5][4];
    {
        const float2* Grow = Gs + row*41;
        if (h == 0) fft40_T<0>(Grow, T);
        else        fft40_T<1>(Grow, T);
    }
    __syncthreads();   // all Gs reads done; region becomes H

    // phase 2b: combine + write H into smem (coefficients independent of u)
    {
        float2* dsts = Hs + blocR*840 + mR;   // + (8s+u)*21
        #pragma unroll
        for (int up = 0; up < 4; up++) {
            int u = 4*h + up;
            #pragma unroll
            for (int s = 0; s < 5; s++) {
                float2 acc = T[0][up];
                #pragma unroll
                for (int r = 1; r < 5; r++)
                    acc = cadd(acc, cmulc(T[r][up], TWC[(8*r*s)%40], TWS[(8*r*s)%40]));
                dsts[(8*s + u) * 21] = acc;
            }
        }
    }
    __syncthreads();

    // phase 3: stage-2 real FFT per (b, g) column + bias + store
    {
        int bloc = t / 40, g = t - bloc*40;
        int b = bg*8 + bloc;
        const float2* col = Hs + (bloc*40 + g)*21;
        float2 hc[20];
        #pragma unroll
        for (int m = 0; m < 20; m++) hc[m] = col[m];
        hc[0].x *= 0.5f; hc[0].y *= 0.5f;
        float bv = bias[zo & 31];
        float* op = out + (size_t)zo*64000 + b*1600 + g;
        const float R2 = 0.70710678f;
        #pragma unroll
        for (int u = 0; u < 8; u++) {
            float2 B[5];
            #pragma unroll
            for (int r = 0; r < 5; r++) {
                float2 acc = hc[r];
                #pragma unroll
                for (int q = 1; q < 4; q++) {
                    int k8 = (q*u) & 7;
                    float c, s;
                    switch (k8) {
                        case 0: c=1.f;  s=0.f;  break;
                        case 1: c=R2;   s=R2;   break;
                        case 2: c=0.f;  s=1.f;  break;
                        case 3: c=-R2;  s=R2;   break;
                        case 4: c=-1.f; s=0.f;  break;
                        case 5: c=-R2;  s=-R2;  break;
                        case 6: c=0.f;  s=-1.f; break;
                        default: c=R2;  s=-R2;  break;
                    }
                    acc = cadd(acc, cmulc(hc[5*q + r], c, s));
                }
                B[r] = cmulc(acc, TWC[(r*u)%40], TWS[(r*u)%40]);
            }
            #pragma unroll
            for (int s = 0; s < 5; s++) {
                float val = B[0].x;
                #pragma unroll
                for (int r = 1; r < 5; r++)
                    val += B[r].x * TWC[(8*r*s)%40] - B[r].y * TWS[(8*r*s)%40];
                op[(8*s + u) * 40] = 2.0f*val + bv;
            }
        }
    }
}

// ---------- launch ----------
extern "C" void kernel_launch(void* const* d_in, const int* in_sizes, int n_in,
                              void* d_out, int out_size) {
    const float* x    = (const float*)d_in[0];
    const float* kern = (const float*)d_in[1];
    const float* bias = (const float*)d_in[2];
    float* out = (float*)d_out;

    cudaFuncSetAttribute(k_zl, cudaFuncAttributeMaxDynamicSharedMemorySize, 105600);
    cudaFuncSetAttribute(k_ho, cudaFuncAttributeMaxDynamicSharedMemorySize, 53760);

    k_init<<<193, 128>>>();
    k_dft<<<dim3(8, 256), 160>>>(x);
    k_xl2cy<<<dim3(45, 16), 512>>>(kern);
    k_zl <<<dim3(32, 16), 256, 105600>>>();
    k_ho <<<dim3(512, 5), 320, 53760>>>(bias, out);
}

// round 13
// speedup vs baseline: 4.8530x; 1.2276x over previous
#include <cuda_runtime.h>
#include <math.h>
#include <stdint.h>

#define PI_D 3.14159265358979323846

// B_IN=64, B_OUT=20, B_INV=20, BATCH=16, F_IN=16, F_OUT=32, N_GRID=24
// half-pair count: sum_l (l+1)(2l+1) = 5530

__constant__ int c_hoff[20]  = {0,1,7,22,50,95,161,252,372,525,715,946,1222,1547,1925,2360,2856,3417,4047,4750};
__constant__ int c_hstep[20] = {1,6,15,28,45,66,91,120,153,190,231,276,325,378,435,496,561,630,703,780};

__device__ float  g_ws2[128*400];      // [beta_b][lm]  lm = l*l + (m+l)
__device__ float2 g_cFk[24*400];       // conj(F_k) [p][lm]
__device__ float4 g_dhA[5*5530];       // (2l+1)*d, betas bg*8+0..3, [bg][hpair]
__device__ float4 g_dhB[5*5530];       // betas bg*8+4..7
__device__ unsigned int g_pinfo[5530]; // (l<<12)|(m<<6)|ni
__device__ float2 g_tw[128*20];        // [a][m] e^{-2pi i a m/128}
__device__ float2 g_Xf[20*128*256];    // [m][b][zi]
__device__ float2 g_xl[16*400*16];     // [z][lm][i]
__device__ float2 g_cy[32*400*16];     // [o][lm][i]
__device__ float2 g_zl[512*5530];      // [zo][hpair]

// e^{+2pi i k/40} tables (static-index use only -> folded to immediates)
__device__ static constexpr float TWC[40] = {
 1.0f, 0.98768834f, 0.95105652f, 0.89100652f, 0.80901699f, 0.70710678f,
 0.58778525f, 0.45399050f, 0.30901699f, 0.15643447f, 0.0f, -0.15643447f,
 -0.30901699f, -0.45399050f, -0.58778525f, -0.70710678f, -0.80901699f,
 -0.89100652f, -0.95105652f, -0.98768834f, -1.0f, -0.98768834f, -0.95105652f,
 -0.89100652f, -0.80901699f, -0.70710678f, -0.58778525f, -0.45399050f,
 -0.30901699f, -0.15643447f, 0.0f, 0.15643447f, 0.30901699f, 0.45399050f,
 0.58778525f, 0.70710678f, 0.80901699f, 0.89100652f, 0.95105652f, 0.98768834f };
__device__ static constexpr float TWS[40] = {
 0.0f, 0.15643447f, 0.30901699f, 0.45399050f, 0.58778525f, 0.70710678f,
 0.80901699f, 0.89100652f, 0.95105652f, 0.98768834f, 1.0f, 0.98768834f,
 0.95105652f, 0.89100652f, 0.80901699f, 0.70710678f, 0.58778525f,
 0.45399050f, 0.30901699f, 0.15643447f, 0.0f, -0.15643447f, -0.30901699f,
 -0.45399050f, -0.58778525f, -0.70710678f, -0.80901699f, -0.89100652f,
 -0.95105652f, -0.98768834f, -1.0f, -0.98768834f, -0.95105652f, -0.89100652f,
 -0.80901699f, -0.70710678f, -0.58778525f, -0.45399050f, -0.30901699f,
 -0.15643447f };

__device__ __forceinline__ float2 cadd(float2 a, float2 b){ return make_float2(a.x+b.x, a.y+b.y); }
__device__ __forceinline__ float2 csub(float2 a, float2 b){ return make_float2(a.x-b.x, a.y-b.y); }
__device__ __forceinline__ float2 cmuli(float2 a){ return make_float2(-a.y, a.x); }      // *i
__device__ __forceinline__ float2 cmulc(float2 a, float c, float s){                     // *(c+is)
    return make_float2(a.x*c - a.y*s, a.x*s + a.y*c);
}

// store one (beta, hpair) value into the split coalesced d-tables
__device__ __forceinline__ void store_d(int b, int hidx, float v) {
    int bb = b & 7, bgi = b >> 3;
    if (bb < 4) ((float*)&g_dhA[bgi*5530 + hidx])[bb] = v;
    else        ((float*)&g_dhB[bgi*5530 + hidx])[bb - 4] = v;
}

// ---------- fp32 Wigner-d: log-space seed + upward 3-term recurrence ----------
__device__ __forceinline__ float wseed(int m, int n, float lcb, float lsb, const float* lf) {
    int am = m < 0 ? -m : m, an = n < 0 ? -n : n;
    int l = am > an ? am : an;
    float v;
    if (am >= an) {
        float lc = 0.5f*(lf[2*l] - lf[l+n] - lf[l-n]);
        if (m >= 0) { v = expf(lc + (l+n)*lcb + (l-n)*lsb); if ((l-n)&1) v = -v; }
        else        { v = expf(lc + (l-n)*lcb + (l+n)*lsb); }
    } else {
        float lc = 0.5f*(lf[2*l] - lf[l+m] - lf[l-m]);
        if (n >= 0) { v = expf(lc + (l+m)*lcb + (l-m)*lsb); }
        else        { v = expf(lc + (l-m)*lcb + (l+m)*lsb); if ((l+m)&1) v = -v; }
    }
    return v;
}

// ---------- combined init kernel ----------
__global__ void k_init() {
    __shared__ float lf[41];
    __shared__ double sterm[64];
    __shared__ double swq;
    int t = threadIdx.x;
    if (t <= 40) lf[t] = lgammaf((float)(t + 1));
    int blk = blockIdx.x;

    if (blk < 128) {
        int b = blk;
        double beta = PI_D * (2.0*b + 1.0) / 256.0;
        if (t < 64) sterm[t] = sin((2.0*t + 1.0) * beta) / (2.0*t + 1.0);
        __syncthreads();
        if (t == 0) {
            double acc = 0.0;
            for (int k = 0; k < 64; k++) acc += sterm[k];
            swq = (2.0/64.0) * sin(beta) * acc;
        }
        __syncthreads();
        float w = (float)swq;
        float cb = (float)cos(beta*0.5), sb = (float)sin(beta*0.5);
        float cosb = (float)cos(beta);
        float lcb = logf(cb), lsb = logf(sb);
        if (t < 39) {
            int m = t - 19;
            int am = m < 0 ? -m : m;
            int l0 = am;
            float d1 = wseed(m, 0, lcb, lsb, lf), d2 = 0.0f;
            g_ws2[b*400 + l0*l0 + l0 + m] = d1 * w;
            int jstart = l0 + 1;
            if (l0 == 0) {
                d2 = d1; d1 = cosb;
                g_ws2[b*400 + 2] = d1 * w;
                jstart = 2;
            }
            for (int j = jstart; j <= 19; j++) {
                float wj  = sqrtf((float)((j*j - m*m) * (j*j)));
                float wj1 = sqrtf((float)(((j-1)*(j-1) - m*m) * ((j-1)*(j-1))));
                float d = ((2*j-1)*((float)(j*(j-1))*cosb) * d1 - (float)j*wj1*d2) / ((float)(j-1)*wj);
                g_ws2[b*400 + j*j + j + m] = d * w;
                d2 = d1; d1 = d;
            }
        }
    } else if (blk < 152) {
        int p = blk - 128;
        __syncthreads();
        double beta  = ((p >> 3) + 1) * PI_D / 24.0;
        float cb = (float)cos(beta*0.5), sb = (float)sin(beta*0.5);
        float cosb = (float)cos(beta);
        float lcb = logf(cb), lsb = logf(sb);
        if (t < 39) {
            int m = t - 19;
            int am = m < 0 ? -m : m;
            int l0 = am;
            float cph, sph;
            sincospif((float)(m * (p & 7)) * 0.25f, &sph, &cph);
            float d1 = wseed(m, 0, lcb, lsb, lf), d2 = 0.0f;
            g_cFk[p*400 + l0*l0 + l0 + m] = make_float2(d1*cph, d1*sph);
            int jstart = l0 + 1;
            if (l0 == 0) {
                d2 = d1; d1 = cosb;
                g_cFk[p*400 + 2] = make_float2(d1*cph, d1*sph);
                jstart = 2;
            }
            for (int j = jstart; j <= 19; j++) {
                float wj  = sqrtf((float)((j*j - m*m) * (j*j)));
                float wj1 = sqrtf((float)(((j-1)*(j-1) - m*m) * ((j-1)*(j-1))));
                float d = ((2*j-1)*((float)(j*(j-1))*cosb) * d1 - (float)j*wj1*d2) / ((float)(j-1)*wj);
                g_cFk[p*400 + j*j + j + m] = make_float2(d*cph, d*sph);
                d2 = d1; d1 = d;
            }
        }
    } else if (blk < 192) {
        int b = blk - 152;
        __syncthreads();
        double beta = PI_D * (2.0*b + 1.0) / 80.0;
        float cb = (float)cos(beta*0.5), sb = (float)sin(beta*0.5);
        float cosb = (float)cos(beta);
        float lcb = logf(cb), lsb = logf(sb);
        for (int p = t; p < 780; p += blockDim.x) {
            int m = p / 39, nj = p % 39, n = nj - 19;
            int an = n < 0 ? -n : n;
            int l0 = m > an ? m : an;
            float d1 = wseed(m, n, lcb, lsb, lf), d2 = 0.0f;
            store_d(b, c_hoff[l0] + m*(2*l0+1) + n + l0, (float)(2*l0+1) * d1);
            int jstart = l0 + 1;
            if (l0 == 0) {
                d2 = d1; d1 = cosb;
                store_d(b, c_hoff[1] + 1, 3.0f * d1);
                jstart = 2;
            }
            float mn = (float)(m * n);
            for (int j = jstart; j <= 19; j++) {
                float wj  = sqrtf((float)((j*j - m*m) * (j*j - n*n)));
                float wj1 = sqrtf((float)(((j-1)*(j-1) - m*m) * ((j-1)*(j-1) - n*n)));
                float d = ((2*j-1)*((float)(j*(j-1))*cosb - mn) * d1 - (float)j*wj1*d2) / ((float)(j-1)*wj);
                store_d(b, c_hoff[j] + m*(2*j+1) + n + j, (float)(2*j+1) * d);
                d2 = d1; d1 = d;
            }
        }
    } else {
        __syncthreads();
        for (int p = t; p < 5530; p += blockDim.x) {
            int l = 0, acc = 0;
            for (; l < 20; l++) {
                int sz = (l+1)*(2*l+1);
                if (p < acc + sz) break;
                acc += sz;
            }
            int r = p - acc, w = 2*l + 1;
            g_pinfo[p] = (unsigned)((l << 12) | ((r / w) << 6) | (r % w));
        }
        for (int idx = t; idx < 2560; idx += blockDim.x) {
            int a = idx / 20, m = idx % 20;
            float s, c;
            sincospif(-(float)(a * m) / 64.0f, &s, &c);
            g_tw[idx] = make_float2(c, s);
        }
    }
}

// ---------- K1: truncated real DFT over alpha via twiddle table ----------
__global__ void k_dft(const float* __restrict__ x) {
    __shared__ float  xs[16][130];
    __shared__ float2 tws[128*20];
    int bg = blockIdx.x, zi = blockIdx.y;
    const float* xp = x + (zi * 128 + bg * 16) * 128;
    for (int idx = threadIdx.x; idx < 2048; idx += 160)
        xs[idx >> 7][idx & 127] = xp[idx];
    for (int idx = threadIdx.x; idx < 2560; idx += 160)
        tws[idx] = g_tw[idx];
    __syncthreads();
    int bp = threadIdx.x / 20;
    int m  = threadIdx.x % 20;
    const float* r0 = xs[2*bp];
    const float* r1 = xs[2*bp + 1];
    float a0r = 0.f, a0i = 0.f, a1r = 0.f, a1i = 0.f;
    #pragma unroll 4
    for (int a = 0; a < 128; a++) {
        float2 w = tws[a*20 + m];
        float x0 = r0[a], x1 = r1[a];
        a0r += x0*w.x; a0i += x0*w.y;
        a1r += x1*w.x; a1i += x1*w.y;
    }
    int b = bg * 16 + 2*bp;
    g_Xf[(m*128 + b    )*256 + zi] = make_float2(a0r, a0i);
    g_Xf[(m*128 + b + 1)*256 + zi] = make_float2(a1r, a1i);
}

// ---------- K2: S2 analysis tiled by (|m|, z), with k_cy work fused as extra blocks ----------
// grid (45, 16): x<20 -> xl2 path (ma=x, z=y); x>=20 -> cy path (lm = (x-20)*16 + y)
__global__ void k_xl2cy(const float* __restrict__ kern) {
    __shared__ float2 Xs[128*16];
    __shared__ float wsp[128*20];
    __shared__ float wsm[128*20];
    __shared__ float2 sF[24];
    int t = threadIdx.x;
    if (blockIdx.x >= 20) {
        // ---- cy path: cy[o][lm][i] = SCALING * conj(y), one block per lm ----
        int lm = (blockIdx.x - 20) * 16 + blockIdx.y;
        if (t < 24) sF[t] = g_cFk[t * 400 + lm];
        __syncthreads();
        int i = t >> 5, o = t & 31;
        const float* kp = kern + (i * 32 + o) * 24;
        float ar = 0.0f, ai = 0.0f;
        for (int p = 0; p < 24; p++) {
            float k = kp[p];
            ar += k * sF[p].x; ai += k * sF[p].y;
        }
        const float S = 0.00816496580927726f;
        g_cy[((size_t)o * 400 + lm) * 16 + i] = make_float2(ar * S, ai * S);
        return;
    }
    // ---- xl2 path ----
    int ma = blockIdx.x, z = blockIdx.y;
    int nl = 20 - ma;
    for (int idx = t; idx < 2048; idx += 512) {
        int b = idx >> 4, i = idx & 15;
        Xs[idx] = g_Xf[(ma*128 + b)*256 + z*16 + i];
    }
    for (int idx = t; idx < 128*nl; idx += 512) {
        int b = idx / nl, li = idx % nl;
        int l = ma + li;
        wsp[idx] = g_ws2[b*400 + l*l + l + ma];
        if (ma > 0) wsm[idx] = g_ws2[b*400 + l*l + l - ma];
    }
    __syncthreads();
    for (int item = t; item < nl*16; item += 512) {
        int li = item >> 4, i = item & 15;
        int l = ma + li;
        float pr = 0.f, pi = 0.f, mr = 0.f, mi = 0.f;
        for (int b = 0; b < 128; b++) {
            float2 xv = Xs[b*16 + i];
            float wp = wsp[b*nl + li];
            pr += wp * xv.x; pi += wp * xv.y;
            if (ma > 0) {
                float wm = wsm[b*nl + li];
                mr += wm * xv.x; mi -= wm * xv.y;
            }
        }
        g_xl[((size_t)z*400 + l*l + l + ma)*16 + i] = make_float2(pr, pi);
        if (ma > 0)
            g_xl[((size_t)z*400 + l*l + l - ma)*16 + i] = make_float2(mr, mi);
    }
}

// ---------- K4: zl[zo][hpair] (512 threads: occupancy 16 -> 32 warps/SM) ----------
__global__ void k_zl() {
    extern __shared__ float2 sm4[];
    float2* xs = sm4;
    float2* cs = sm4 + 6400;
    int o = blockIdx.x, z = blockIdx.y;
    for (int idx = threadIdx.x; idx < 6400; idx += blockDim.x) {
        xs[idx] = g_xl[(size_t)z * 6400 + idx];
        int lm = idx >> 4, i = idx & 15;
        cs[lm * 17 + i] = g_cy[(size_t)o * 6400 + idx];
    }
    __syncthreads();
    float2* outp = g_zl + (size_t)(z * 32 + o) * 5530;
    for (int p = threadIdx.x; p < 5530; p += blockDim.x) {
        unsigned info = g_pinfo[p];
        int l = info >> 12, m = (info >> 6) & 63, ni = info & 63;
        const float2* A  = xs + (l*l + l + m) * 16;
        const float2* Bc = cs + (l*l + ni) * 17;
        float ar = 0.0f, ai = 0.0f;
        #pragma unroll
        for (int i = 0; i < 16; i++) {
            float2 a = A[i], c = Bc[i];
            ar += a.x*c.x - a.y*c.y;
            ai += a.x*c.y + a.y*c.x;
        }
        outp[p] = make_float2(ar, ai);
    }
}

// ---------- stage1 40-pt FFT partials: T[r][up] for u = 4*HH+up ----------
template<int HH>
__device__ __forceinline__ void fft40_T(const float2* __restrict__ Grow, float2 T[5][4]) {
    const float R2 = 0.70710678f;
    #pragma unroll
    for (int r = 0; r < 5; r++) {
        float2 x0=Grow[r],    x1=Grow[5+r],  x2=Grow[10+r], x3=Grow[15+r];
        float2 x4=Grow[20+r], x5=Grow[25+r], x6=Grow[30+r], x7=Grow[35+r];
        float2 a04=cadd(x0,x4), s04=csub(x0,x4);
        float2 a26=cadd(x2,x6), s26=csub(x2,x6);
        float2 E0=cadd(a04,a26), E1=cadd(s04,cmuli(s26));
        float2 E2=csub(a04,a26), E3=csub(s04,cmuli(s26));
        float2 a15=cadd(x1,x5), s15=csub(x1,x5);
        float2 a37=cadd(x3,x7), s37=csub(x3,x7);
        float2 O0=cadd(a15,a37), O1=cadd(s15,cmuli(s37));
        float2 O2=csub(a15,a37), O3=csub(s15,cmuli(s37));
        float2 w1o = make_float2(R2*(O1.x-O1.y), R2*(O1.x+O1.y));  // W8^1 * O1
        float2 w2o = cmuli(O2);                                     // W8^2 * O2
        float2 w3o = make_float2(-R2*(O3.x+O3.y), R2*(O3.x-O3.y)); // W8^3 * O3
        float2 y0, y1, y2, y3;
        if (HH == 0) { y0=cadd(E0,O0); y1=cadd(E1,w1o); y2=cadd(E2,w2o); y3=cadd(E3,w3o); }
        else         { y0=csub(E0,O0); y1=csub(E1,w1o); y2=csub(E2,w2o); y3=csub(E3,w3o); }
        T[r][0] = cmulc(y0, TWC[(r*(4*HH+0))%40], TWS[(r*(4*HH+0))%40]);
        T[r][1] = cmulc(y1, TWC[(r*(4*HH+1))%40], TWS[(r*(4*HH+1))%40]);
        T[r][2] = cmulc(y2, TWC[(r*(4*HH+2))%40], TWS[(r*(4*HH+2))%40]);
        T[r][3] = cmulc(y3, TWC[(r*(4*HH+3))%40], TWS[(r*(4*HH+3))%40]);
    }
}

// ---------- K5 fused: register-blocked G-build + stage1 FFT + stage2 + output ----------
// occupancy 2 (not 3): ~102 regs/thread available -> no spills in the unrolled FFT phases
__global__ void __launch_bounds__(320, 2) k_ho(const float* __restrict__ bias,
                                               float* __restrict__ out) {
    extern __shared__ float2 sm5[];
    float2* Gs = sm5;
    float2* Hs = sm5;
    int zo = blockIdx.x, bg = blockIdx.y;
    int t = threadIdx.x;

    // phase 1: build G for 8 betas at once (register-blocked over beta, coalesced d)
    const float2* zrow = g_zl + (size_t)zo * 5530;
    const float4* dA = g_dhA + bg * 5530;
    const float4* dB = g_dhB + bg * 5530;
    for (int e = t; e < 800; e += 320) {
        int m = e / 40, j = e % 40;
        int n = (j <= 19) ? j : j - 40;
        int an = n < 0 ? -n : n;
        int lmin = m > an ? m : an;
        int idx = c_hoff[lmin] + m*(2*lmin + 1) + (n + lmin);
        int inc = 2*m + 1;
        float gr0=0.f,gi0=0.f,gr1=0.f,gi1=0.f,gr2=0.f,gi2=0.f,gr3=0.f,gi3=0.f;
        float gr4=0.f,gi4=0.f,gr5=0.f,gi5=0.f,gr6=0.f,gi6=0.f,gr7=0.f,gi7=0.f;
        for (int l = lmin; l < 20; l++) {
            float2 zv = __ldg(zrow + idx);
            float4 d0 = __ldg(dA + idx);
            float4 d1 = __ldg(dB + idx);
            gr0 += zv.x*d0.x; gi0 += zv.y*d0.x;
            gr1 += zv.x*d0.y; gi1 += zv.y*d0.y;
            gr2 += zv.x*d0.z; gi2 += zv.y*d0.z;
            gr3 += zv.x*d0.w; gi3 += zv.y*d0.w;
            gr4 += zv.x*d1.x; gi4 += zv.y*d1.x;
            gr5 += zv.x*d1.y; gi5 += zv.y*d1.y;
            gr6 += zv.x*d1.z; gi6 += zv.y*d1.z;
            gr7 += zv.x*d1.w; gi7 += zv.y*d1.w;
            idx += c_hstep[l] + inc;
        }
        int base = m*41 + j;
        Gs[base        ] = make_float2(gr0, gi0);
        Gs[base +  820 ] = make_float2(gr1, gi1);
        Gs[base + 1640 ] = make_float2(gr2, gi2);
        Gs[base + 2460 ] = make_float2(gr3, gi3);
        Gs[base + 3280 ] = make_float2(gr4, gi4);
        Gs[base + 4100 ] = make_float2(gr5, gi5);
        Gs[base + 4920 ] = make_float2(gr6, gi6);
        Gs[base + 5740 ] = make_float2(gr7, gi7);
    }
    __syncthreads();

    // phase 2a: stage-1 FFT partials in registers (reads Gs only)
    int h = t / 160, row = t - h*160;
    int blocR = row / 20, mR = row % 20;
    float2 T[5][4];
    {
        const float2* Grow = Gs + row*41;
        if (h == 0) fft40_T<0>(Grow, T);
        else        fft40_T<1>(Grow, T);
    }
    __syncthreads();   // all Gs reads done; region becomes H

    // phase 2b: combine + write H into smem (coefficients independent of u)
    {
        float2* dsts = Hs + blocR*840 + mR;   // + (8s+u)*21
        #pragma unroll
        for (int up = 0; up < 4; up++) {
            int u = 4*h + up;
            #pragma unroll
            for (int s = 0; s < 5; s++) {
                float2 acc = T[0][up];
                #pragma unroll
                for (int r = 1; r < 5; r++)
                    acc = cadd(acc, cmulc(T[r][up], TWC[(8*r*s)%40], TWS[(8*r*s)%40]));
                dsts[(8*s + u) * 21] = acc;
            }
        }
    }
    __syncthreads();

    // phase 3: stage-2 real FFT per (b, g) column + bias + store
    {
        int bloc = t / 40, g = t - bloc*40;
        int b = bg*8 + bloc;
        const float2* col = Hs + (bloc*40 + g)*21;
        float2 hc[20];
        #pragma unroll
        for (int m = 0; m < 20; m++) hc[m] = col[m];
        hc[0].x *= 0.5f; hc[0].y *= 0.5f;
        float bv = bias[zo & 31];
        float* op = out + (size_t)zo*64000 + b*1600 + g;
        const float R2 = 0.70710678f;
        #pragma unroll
        for (int u = 0; u < 8; u++) {
            float2 B[5];
            #pragma unroll
            for (int r = 0; r < 5; r++) {
                float2 acc = hc[r];
                #pragma unroll
                for (int q = 1; q < 4; q++) {
                    int k8 = (q*u) & 7;
                    float c, s;
                    switch (k8) {
                        case 0: c=1.f;  s=0.f;  break;
                        case 1: c=R2;   s=R2;   break;
                        case 2: c=0.f;  s=1.f;  break;
                        case 3: c=-R2;  s=R2;   break;
                        case 4: c=-1.f; s=0.f;  break;
                        case 5: c=-R2;  s=-R2;  break;
                        case 6: c=0.f;  s=-1.f; break;
                        default: c=R2;  s=-R2;  break;
                    }
                    acc = cadd(acc, cmulc(hc[5*q + r], c, s));
                }
                B[r] = cmulc(acc, TWC[(r*u)%40], TWS[(r*u)%40]);
            }
            #pragma unroll
            for (int s = 0; s < 5; s++) {
                float val = B[0].x;
                #pragma unroll
                for (int r = 1; r < 5; r++)
                    val += B[r].x * TWC[(8*r*s)%40] - B[r].y * TWS[(8*r*s)%40];
                op[(8*s + u) * 40] = 2.0f*val + bv;
            }
        }
    }
}

// ---------- launch ----------
extern "C" void kernel_launch(void* const* d_in, const int* in_sizes, int n_in,
                              void* d_out, int out_size) {
    const float* x    = (const float*)d_in[0];
    const float* kern = (const float*)d_in[1];
    const float* bias = (const float*)d_in[2];
    float* out = (float*)d_out;

    cudaFuncSetAttribute(k_zl, cudaFuncAttributeMaxDynamicSharedMemorySize, 105600);
    cudaFuncSetAttribute(k_ho, cudaFuncAttributeMaxDynamicSharedMemorySize, 53760);

    k_init<<<193, 128>>>();
    k_dft<<<dim3(8, 256), 160>>>(x);
    k_xl2cy<<<dim3(45, 16), 512>>>(kern);
    k_zl <<<dim3(32, 16), 512, 105600>>>();
    k_ho <<<dim3(512, 5), 320, 53760>>>(bias, out);
}

// round 14
// speedup vs baseline: 4.9086x; 1.0115x over previous
#include <cuda_runtime.h>
#include <math.h>
#include <stdint.h>

#define PI_D 3.14159265358979323846

// B_IN=64, B_OUT=20, B_INV=20, BATCH=16, F_IN=16, F_OUT=32, N_GRID=24
// half-pair count: sum_l (l+1)(2l+1) = 5530

__constant__ int c_hoff[20]  = {0,1,7,22,50,95,161,252,372,525,715,946,1222,1547,1925,2360,2856,3417,4047,4750};
__constant__ int c_hstep[20] = {1,6,15,28,45,66,91,120,153,190,231,276,325,378,435,496,561,630,703,780};

__device__ float  g_ws2[128*400];      // [beta_b][lm]  lm = l*l + (m+l)
__device__ float2 g_cFk[24*400];       // conj(F_k) [p][lm]
__device__ float4 g_dhA[5*5530];       // (2l+1)*d, betas bg*8+0..3, [bg][hpair]
__device__ float4 g_dhB[5*5530];       // betas bg*8+4..7
__device__ unsigned int g_pinfo[5530]; // (l<<12)|(m<<6)|ni
__device__ float2 g_tw[128*20];        // [a][m] e^{-2pi i a m/128}
__device__ float2 g_Xf[20*128*256];    // [m][b][zi]
__device__ float2 g_xl[16*400*16];     // [z][lm][i]
__device__ float2 g_cy[32*400*16];     // [o][lm][i]
__device__ float2 g_zl[512*5530];      // [zo][hpair]

// e^{+2pi i k/40} tables (static-index use only -> folded to immediates)
__device__ static constexpr float TWC[40] = {
 1.0f, 0.98768834f, 0.95105652f, 0.89100652f, 0.80901699f, 0.70710678f,
 0.58778525f, 0.45399050f, 0.30901699f, 0.15643447f, 0.0f, -0.15643447f,
 -0.30901699f, -0.45399050f, -0.58778525f, -0.70710678f, -0.80901699f,
 -0.89100652f, -0.95105652f, -0.98768834f, -1.0f, -0.98768834f, -0.95105652f,
 -0.89100652f, -0.80901699f, -0.70710678f, -0.58778525f, -0.45399050f,
 -0.30901699f, -0.15643447f, 0.0f, 0.15643447f, 0.30901699f, 0.45399050f,
 0.58778525f, 0.70710678f, 0.80901699f, 0.89100652f, 0.95105652f, 0.98768834f };
__device__ static constexpr float TWS[40] = {
 0.0f, 0.15643447f, 0.30901699f, 0.45399050f, 0.58778525f, 0.70710678f,
 0.80901699f, 0.89100652f, 0.95105652f, 0.98768834f, 1.0f, 0.98768834f,
 0.95105652f, 0.89100652f, 0.80901699f, 0.70710678f, 0.58778525f,
 0.45399050f, 0.30901699f, 0.15643447f, 0.0f, -0.15643447f, -0.30901699f,
 -0.45399050f, -0.58778525f, -0.70710678f, -0.80901699f, -0.89100652f,
 -0.95105652f, -0.98768834f, -1.0f, -0.98768834f, -0.95105652f, -0.89100652f,
 -0.80901699f, -0.70710678f, -0.58778525f, -0.45399050f, -0.30901699f,
 -0.15643447f };
// e^{+2pi i k/8}
__device__ static constexpr float W8C[8] = {1.f,0.70710678f,0.f,-0.70710678f,-1.f,-0.70710678f,0.f,0.70710678f};
__device__ static constexpr float W8S[8] = {0.f,0.70710678f,1.f,0.70710678f,0.f,-0.70710678f,-1.f,-0.70710678f};

__device__ __forceinline__ float2 cadd(float2 a, float2 b){ return make_float2(a.x+b.x, a.y+b.y); }
__device__ __forceinline__ float2 csub(float2 a, float2 b){ return make_float2(a.x-b.x, a.y-b.y); }
__device__ __forceinline__ float2 cmuli(float2 a){ return make_float2(-a.y, a.x); }      // *i
__device__ __forceinline__ float2 cmulni(float2 a){ return make_float2(a.y, -a.x); }     // *(-i)
__device__ __forceinline__ float2 cmulc(float2 a, float c, float s){                     // *(c+is)
    return make_float2(a.x*c - a.y*s, a.x*s + a.y*c);
}

// store one (beta, hpair) value into the split coalesced d-tables
__device__ __forceinline__ void store_d(int b, int hidx, float v) {
    int bb = b & 7, bgi = b >> 3;
    if (bb < 4) ((float*)&g_dhA[bgi*5530 + hidx])[bb] = v;
    else        ((float*)&g_dhB[bgi*5530 + hidx])[bb - 4] = v;
}

// ---------- fp32 Wigner-d: log-space seed + upward 3-term recurrence ----------
__device__ __forceinline__ float wseed(int m, int n, float lcb, float lsb, const float* lf) {
    int am = m < 0 ? -m : m, an = n < 0 ? -n : n;
    int l = am > an ? am : an;
    float v;
    if (am >= an) {
        float lc = 0.5f*(lf[2*l] - lf[l+n] - lf[l-n]);
        if (m >= 0) { v = expf(lc + (l+n)*lcb + (l-n)*lsb); if ((l-n)&1) v = -v; }
        else        { v = expf(lc + (l-n)*lcb + (l+n)*lsb); }
    } else {
        float lc = 0.5f*(lf[2*l] - lf[l+m] - lf[l-m]);
        if (n >= 0) { v = expf(lc + (l+m)*lcb + (l-m)*lsb); }
        else        { v = expf(lc + (l-m)*lcb + (l+m)*lsb); if ((l+m)&1) v = -v; }
    }
    return v;
}

// ---------- combined init kernel ----------
__global__ void k_init() {
    __shared__ float lf[41];
    __shared__ double sterm[64];
    __shared__ double swq;
    int t = threadIdx.x;
    if (t <= 40) lf[t] = lgammaf((float)(t + 1));
    int blk = blockIdx.x;

    if (blk < 128) {
        int b = blk;
        double beta = PI_D * (2.0*b + 1.0) / 256.0;
        if (t < 64) sterm[t] = sin((2.0*t + 1.0) * beta) / (2.0*t + 1.0);
        __syncthreads();
        if (t == 0) {
            double acc = 0.0;
            for (int k = 0; k < 64; k++) acc += sterm[k];
            swq = (2.0/64.0) * sin(beta) * acc;
        }
        __syncthreads();
        float w = (float)swq;
        float cb = (float)cos(beta*0.5), sb = (float)sin(beta*0.5);
        float cosb = (float)cos(beta);
        float lcb = logf(cb), lsb = logf(sb);
        if (t < 39) {
            int m = t - 19;
            int am = m < 0 ? -m : m;
            int l0 = am;
            float d1 = wseed(m, 0, lcb, lsb, lf), d2 = 0.0f;
            g_ws2[b*400 + l0*l0 + l0 + m] = d1 * w;
            int jstart = l0 + 1;
            if (l0 == 0) {
                d2 = d1; d1 = cosb;
                g_ws2[b*400 + 2] = d1 * w;
                jstart = 2;
            }
            for (int j = jstart; j <= 19; j++) {
                float wj  = sqrtf((float)((j*j - m*m) * (j*j)));
                float wj1 = sqrtf((float)(((j-1)*(j-1) - m*m) * ((j-1)*(j-1))));
                float d = ((2*j-1)*((float)(j*(j-1))*cosb) * d1 - (float)j*wj1*d2) / ((float)(j-1)*wj);
                g_ws2[b*400 + j*j + j + m] = d * w;
                d2 = d1; d1 = d;
            }
        }
    } else if (blk < 152) {
        int p = blk - 128;
        __syncthreads();
        double beta  = ((p >> 3) + 1) * PI_D / 24.0;
        float cb = (float)cos(beta*0.5), sb = (float)sin(beta*0.5);
        float cosb = (float)cos(beta);
        float lcb = logf(cb), lsb = logf(sb);
        if (t < 39) {
            int m = t - 19;
            int am = m < 0 ? -m : m;
            int l0 = am;
            float cph, sph;
            sincospif((float)(m * (p & 7)) * 0.25f, &sph, &cph);
            float d1 = wseed(m, 0, lcb, lsb, lf), d2 = 0.0f;
            g_cFk[p*400 + l0*l0 + l0 + m] = make_float2(d1*cph, d1*sph);
            int jstart = l0 + 1;
            if (l0 == 0) {
                d2 = d1; d1 = cosb;
                g_cFk[p*400 + 2] = make_float2(d1*cph, d1*sph);
                jstart = 2;
            }
            for (int j = jstart; j <= 19; j++) {
                float wj  = sqrtf((float)((j*j - m*m) * (j*j)));
                float wj1 = sqrtf((float)(((j-1)*(j-1) - m*m) * ((j-1)*(j-1))));
                float d = ((2*j-1)*((float)(j*(j-1))*cosb) * d1 - (float)j*wj1*d2) / ((float)(j-1)*wj);
                g_cFk[p*400 + j*j + j + m] = make_float2(d*cph, d*sph);
                d2 = d1; d1 = d;
            }
        }
    } else if (blk < 192) {
        int b = blk - 152;
        __syncthreads();
        double beta = PI_D * (2.0*b + 1.0) / 80.0;
        float cb = (float)cos(beta*0.5), sb = (float)sin(beta*0.5);
        float cosb = (float)cos(beta);
        float lcb = logf(cb), lsb = logf(sb);
        for (int p = t; p < 780; p += blockDim.x) {
            int m = p / 39, nj = p % 39, n = nj - 19;
            int an = n < 0 ? -n : n;
            int l0 = m > an ? m : an;
            float d1 = wseed(m, n, lcb, lsb, lf), d2 = 0.0f;
            store_d(b, c_hoff[l0] + m*(2*l0+1) + n + l0, (float)(2*l0+1) * d1);
            int jstart = l0 + 1;
            if (l0 == 0) {
                d2 = d1; d1 = cosb;
                store_d(b, c_hoff[1] + 1, 3.0f * d1);
                jstart = 2;
            }
            float mn = (float)(m * n);
            for (int j = jstart; j <= 19; j++) {
                float wj  = sqrtf((float)((j*j - m*m) * (j*j - n*n)));
                float wj1 = sqrtf((float)(((j-1)*(j-1) - m*m) * ((j-1)*(j-1) - n*n)));
                float d = ((2*j-1)*((float)(j*(j-1))*cosb - mn) * d1 - (float)j*wj1*d2) / ((float)(j-1)*wj);
                store_d(b, c_hoff[j] + m*(2*j+1) + n + j, (float)(2*j+1) * d);
                d2 = d1; d1 = d;
            }
        }
    } else {
        __syncthreads();
        for (int p = t; p < 5530; p += blockDim.x) {
            int l = 0, acc = 0;
            for (; l < 20; l++) {
                int sz = (l+1)*(2*l+1);
                if (p < acc + sz) break;
                acc += sz;
            }
            int r = p - acc, w = 2*l + 1;
            g_pinfo[p] = (unsigned)((l << 12) | ((r / w) << 6) | (r % w));
        }
        for (int idx = t; idx < 2560; idx += blockDim.x) {
            int a = idx / 20, m = idx % 20;
            float s, c;
            sincospif(-(float)(a * m) / 64.0f, &s, &c);
            g_tw[idx] = make_float2(c, s);
        }
    }
}

// ---------- K1: truncated real DFT over alpha via twiddle table ----------
__global__ void k_dft(const float* __restrict__ x) {
    __shared__ float  xs[16][130];
    __shared__ float2 tws[128*20];
    int bg = blockIdx.x, zi = blockIdx.y;
    const float* xp = x + (zi * 128 + bg * 16) * 128;
    for (int idx = threadIdx.x; idx < 2048; idx += 160)
        xs[idx >> 7][idx & 127] = xp[idx];
    for (int idx = threadIdx.x; idx < 2560; idx += 160)
        tws[idx] = g_tw[idx];
    __syncthreads();
    int bp = threadIdx.x / 20;
    int m  = threadIdx.x % 20;
    const float* r0 = xs[2*bp];
    const float* r1 = xs[2*bp + 1];
    float a0r = 0.f, a0i = 0.f, a1r = 0.f, a1i = 0.f;
    #pragma unroll 4
    for (int a = 0; a < 128; a++) {
        float2 w = tws[a*20 + m];
        float x0 = r0[a], x1 = r1[a];
        a0r += x0*w.x; a0i += x0*w.y;
        a1r += x1*w.x; a1i += x1*w.y;
    }
    int b = bg * 16 + 2*bp;
    g_Xf[(m*128 + b    )*256 + zi] = make_float2(a0r, a0i);
    g_Xf[(m*128 + b + 1)*256 + zi] = make_float2(a1r, a1i);
}

// ---------- K2: S2 analysis tiled by (|m|, z), with k_cy work fused as extra blocks ----------
// grid (45, 16): x<20 -> xl2 path (ma=x, z=y); x>=20 -> cy path (lm = (x-20)*16 + y)
__global__ void k_xl2cy(const float* __restrict__ kern) {
    __shared__ float2 Xs[128*16];
    __shared__ float wsp[128*20];
    __shared__ float wsm[128*20];
    __shared__ float2 sF[24];
    int t = threadIdx.x;
    if (blockIdx.x >= 20) {
        // ---- cy path ----
        int lm = (blockIdx.x - 20) * 16 + blockIdx.y;
        if (t < 24) sF[t] = g_cFk[t * 400 + lm];
        __syncthreads();
        int i = t >> 5, o = t & 31;
        const float* kp = kern + (i * 32 + o) * 24;
        float ar = 0.0f, ai = 0.0f;
        for (int p = 0; p < 24; p++) {
            float k = kp[p];
            ar += k * sF[p].x; ai += k * sF[p].y;
        }
        const float S = 0.00816496580927726f;
        g_cy[((size_t)o * 400 + lm) * 16 + i] = make_float2(ar * S, ai * S);
        return;
    }
    // ---- xl2 path ----
    int ma = blockIdx.x, z = blockIdx.y;
    int nl = 20 - ma;
    for (int idx = t; idx < 2048; idx += 512) {
        int b = idx >> 4, i = idx & 15;
        Xs[idx] = g_Xf[(ma*128 + b)*256 + z*16 + i];
    }
    for (int idx = t; idx < 128*nl; idx += 512) {
        int b = idx / nl, li = idx % nl;
        int l = ma + li;
        wsp[idx] = g_ws2[b*400 + l*l + l + ma];
        if (ma > 0) wsm[idx] = g_ws2[b*400 + l*l + l - ma];
    }
    __syncthreads();
    for (int item = t; item < nl*16; item += 512) {
        int li = item >> 4, i = item & 15;
        int l = ma + li;
        float pr = 0.f, pi = 0.f, mr = 0.f, mi = 0.f;
        for (int b = 0; b < 128; b++) {
            float2 xv = Xs[b*16 + i];
            float wp = wsp[b*nl + li];
            pr += wp * xv.x; pi += wp * xv.y;
            if (ma > 0) {
                float wm = wsm[b*nl + li];
                mr += wm * xv.x; mi -= wm * xv.y;
            }
        }
        g_xl[((size_t)z*400 + l*l + l + ma)*16 + i] = make_float2(pr, pi);
        if (ma > 0)
            g_xl[((size_t)z*400 + l*l + l - ma)*16 + i] = make_float2(mr, mi);
    }
}

// ---------- K4: zl[zo][hpair], LDS.128 vectorized (cs pitch 18 keeps 16B alignment) ----------
__global__ void k_zl() {
    extern __shared__ float2 sm4[];
    float2* xs = sm4;            // [lm][i] 400*16
    float2* cs = sm4 + 6400;     // [lm][i] pitch 18 (16B-aligned rows)
    int o = blockIdx.x, z = blockIdx.y;
    for (int idx = threadIdx.x; idx < 6400; idx += blockDim.x) {
        xs[idx] = g_xl[(size_t)z * 6400 + idx];
        int lm = idx >> 4, i = idx & 15;
        cs[lm * 18 + i] = g_cy[(size_t)o * 6400 + idx];
    }
    __syncthreads();
    float2* outp = g_zl + (size_t)(z * 32 + o) * 5530;
    for (int p = threadIdx.x; p < 5530; p += blockDim.x) {
        unsigned info = g_pinfo[p];
        int l = info >> 12, m = (info >> 6) & 63, ni = info & 63;
        const float4* A4 = (const float4*)(xs + (l*l + l + m) * 16);
        const float4* B4 = (const float4*)(cs + (l*l + ni) * 18);
        float ar = 0.0f, ai = 0.0f;
        #pragma unroll
        for (int i = 0; i < 8; i++) {
            float4 a = A4[i], c = B4[i];
            ar += a.x*c.x - a.y*c.y;
            ai += a.x*c.y + a.y*c.x;
            ar += a.z*c.z - a.w*c.w;
            ai += a.z*c.w + a.w*c.z;
        }
        outp[p] = make_float2(ar, ai);
    }
}

// ---------- stage1 40-pt FFT partials: T[r][up] for u = 4*HH+up ----------
template<int HH>
__device__ __forceinline__ void fft40_T(const float2* __restrict__ Grow, float2 T[5][4]) {
    const float R2 = 0.70710678f;
    #pragma unroll
    for (int r = 0; r < 5; r++) {
        float2 x0=Grow[r],    x1=Grow[5+r],  x2=Grow[10+r], x3=Grow[15+r];
        float2 x4=Grow[20+r], x5=Grow[25+r], x6=Grow[30+r], x7=Grow[35+r];
        float2 a04=cadd(x0,x4), s04=csub(x0,x4);
        float2 a26=cadd(x2,x6), s26=csub(x2,x6);
        float2 E0=cadd(a04,a26), E1=cadd(s04,cmuli(s26));
        float2 E2=csub(a04,a26), E3=csub(s04,cmuli(s26));
        float2 a15=cadd(x1,x5), s15=csub(x1,x5);
        float2 a37=cadd(x3,x7), s37=csub(x3,x7);
        float2 O0=cadd(a15,a37), O1=cadd(s15,cmuli(s37));
        float2 O2=csub(a15,a37), O3=csub(s15,cmuli(s37));
        float2 w1o = make_float2(R2*(O1.x-O1.y), R2*(O1.x+O1.y));  // W8^1 * O1
        float2 w2o = cmuli(O2);                                     // W8^2 * O2
        float2 w3o = make_float2(-R2*(O3.x+O3.y), R2*(O3.x-O3.y)); // W8^3 * O3
        float2 y0, y1, y2, y3;
        if (HH == 0) { y0=cadd(E0,O0); y1=cadd(E1,w1o); y2=cadd(E2,w2o); y3=cadd(E3,w3o); }
        else         { y0=csub(E0,O0); y1=csub(E1,w1o); y2=csub(E2,w2o); y3=csub(E3,w3o); }
        T[r][0] = cmulc(y0, TWC[(r*(4*HH+0))%40], TWS[(r*(4*HH+0))%40]);
        T[r][1] = cmulc(y1, TWC[(r*(4*HH+1))%40], TWS[(r*(4*HH+1))%40]);
        T[r][2] = cmulc(y2, TWC[(r*(4*HH+2))%40], TWS[(r*(4*HH+2))%40]);
        T[r][3] = cmulc(y3, TWC[(r*(4*HH+3))%40], TWS[(r*(4*HH+3))%40]);
    }
}

// ---------- K5 fused: register-blocked G-build + stage1 FFT + stage2 + output ----------
// H pitch 22 (16B-aligned columns for LDS.128); smem = max(G 6560, H 7040) = 7040 float2
__global__ void __launch_bounds__(320, 2) k_ho(const float* __restrict__ bias,
                                               float* __restrict__ out) {
    extern __shared__ float2 sm5[];
    float2* Gs = sm5;
    float2* Hs = sm5;
    int zo = blockIdx.x, bg = blockIdx.y;
    int t = threadIdx.x;

    // phase 1: build G for 8 betas at once (register-blocked over beta, coalesced d)
    const float2* zrow = g_zl + (size_t)zo * 5530;
    const float4* dA = g_dhA + bg * 5530;
    const float4* dB = g_dhB + bg * 5530;
    for (int e = t; e < 800; e += 320) {
        int m = e / 40, j = e % 40;
        int n = (j <= 19) ? j : j - 40;
        int an = n < 0 ? -n : n;
        int lmin = m > an ? m : an;
        int idx = c_hoff[lmin] + m*(2*lmin + 1) + (n + lmin);
        int inc = 2*m + 1;
        float gr0=0.f,gi0=0.f,gr1=0.f,gi1=0.f,gr2=0.f,gi2=0.f,gr3=0.f,gi3=0.f;
        float gr4=0.f,gi4=0.f,gr5=0.f,gi5=0.f,gr6=0.f,gi6=0.f,gr7=0.f,gi7=0.f;
        for (int l = lmin; l < 20; l++) {
            float2 zv = __ldg(zrow + idx);
            float4 d0 = __ldg(dA + idx);
            float4 d1 = __ldg(dB + idx);
            gr0 += zv.x*d0.x; gi0 += zv.y*d0.x;
            gr1 += zv.x*d0.y; gi1 += zv.y*d0.y;
            gr2 += zv.x*d0.z; gi2 += zv.y*d0.z;
            gr3 += zv.x*d0.w; gi3 += zv.y*d0.w;
            gr4 += zv.x*d1.x; gi4 += zv.y*d1.x;
            gr5 += zv.x*d1.y; gi5 += zv.y*d1.y;
            gr6 += zv.x*d1.z; gi6 += zv.y*d1.z;
            gr7 += zv.x*d1.w; gi7 += zv.y*d1.w;
            idx += c_hstep[l] + inc;
        }
        int base = m*41 + j;
        Gs[base        ] = make_float2(gr0, gi0);
        Gs[base +  820 ] = make_float2(gr1, gi1);
        Gs[base + 1640 ] = make_float2(gr2, gi2);
        Gs[base + 2460 ] = make_float2(gr3, gi3);
        Gs[base + 3280 ] = make_float2(gr4, gi4);
        Gs[base + 4100 ] = make_float2(gr5, gi5);
        Gs[base + 4920 ] = make_float2(gr6, gi6);
        Gs[base + 5740 ] = make_float2(gr7, gi7);
    }
    __syncthreads();

    // phase 2a: stage-1 FFT partials in registers (reads Gs only)
    int h = t / 160, row = t - h*160;
    int blocR = row / 20, mR = row % 20;
    float2 T[5][4];
    {
        const float2* Grow = Gs + row*41;
        if (h == 0) fft40_T<0>(Grow, T);
        else        fft40_T<1>(Grow, T);
    }
    __syncthreads();   // all Gs reads done; region becomes H

    // phase 2b: combine + write H into smem (pitch 22)
    {
        float2* dsts = Hs + blocR*880 + mR;   // + (8s+u)*22
        #pragma unroll
        for (int up = 0; up < 4; up++) {
            int u = 4*h + up;
            #pragma unroll
            for (int s = 0; s < 5; s++) {
                float2 acc = T[0][up];
                #pragma unroll
                for (int r = 1; r < 5; r++)
                    acc = cadd(acc, cmulc(T[r][up], TWC[(8*r*s)%40], TWS[(8*r*s)%40]));
                dsts[(8*s + u) * 22] = acc;
            }
        }
    }
    __syncthreads();

    // phase 3: stage-2 real FFT per (b, g) column, u/(u+4) radix-2 pairing
    {
        int bloc = t / 40, g = t - bloc*40;
        int b = bg*8 + bloc;
        const float4* col4 = (const float4*)(Hs + (bloc*40 + g)*22);
        float2 hc[20];
        #pragma unroll
        for (int k = 0; k < 10; k++) {
            float4 v = col4[k];
            hc[2*k]   = make_float2(v.x, v.y);
            hc[2*k+1] = make_float2(v.z, v.w);
        }
        hc[0].x *= 0.5f; hc[0].y *= 0.5f;
        float bv = bias[zo & 31];
        float* op = out + (size_t)zo*64000 + b*1600 + g;
        #pragma unroll
        for (int u = 0; u < 4; u++) {
            float2 B0[5], B1[5];
            #pragma unroll
            for (int r = 0; r < 5; r++) {
                // P = even-q terms: hc[r] + hc[10+r]*W8^{2u} (W8^{2u} in {1,i,-1,-i})
                float2 h2 = hc[10 + r];
                float2 t2;
                if      (u == 0) t2 = h2;
                else if (u == 1) t2 = cmuli(h2);
                else if (u == 2) t2 = make_float2(-h2.x, -h2.y);
                else             t2 = cmulni(h2);
                float2 P = cadd(hc[r], t2);
                // Q = odd-q terms: hc[5+r]*W8^u + hc[15+r]*W8^{3u}
                float2 Q = cadd(cmulc(hc[5 + r],  W8C[u],        W8S[u]),
                                cmulc(hc[15 + r], W8C[(3*u)&7],  W8S[(3*u)&7]));
                float2 Au = cadd(P, Q);     // A[u]
                float2 Av = csub(P, Q);     // A[u+4]
                B0[r] = cmulc(Au, TWC[(r*u)%40],     TWS[(r*u)%40]);
                B1[r] = cmulc(Av, TWC[(r*(u+4))%40], TWS[(r*(u+4))%40]);
            }
            #pragma unroll
            for (int s = 0; s < 5; s++) {
                float v0 = B0[0].x, v1 = B1[0].x;
                #pragma unroll
                for (int r = 1; r < 5; r++) {
                    v0 += B0[r].x * TWC[(8*r*s)%40] - B0[r].y * TWS[(8*r*s)%40];
                    v1 += B1[r].x * TWC[(8*r*s)%40] - B1[r].y * TWS[(8*r*s)%40];
                }
                op[(8*s + u    ) * 40] = 2.0f*v0 + bv;
                op[(8*s + u + 4) * 40] = 2.0f*v1 + bv;
            }
        }
    }
}

// ---------- launch ----------
extern "C" void kernel_launch(void* const* d_in, const int* in_sizes, int n_in,
                              void* d_out, int out_size) {
    const float* x    = (const float*)d_in[0];
    const float* kern = (const float*)d_in[1];
    const float* bias = (const float*)d_in[2];
    float* out = (float*)d_out;

    cudaFuncSetAttribute(k_zl, cudaFuncAttributeMaxDynamicSharedMemorySize, 108800);
    cudaFuncSetAttribute(k_ho, cudaFuncAttributeMaxDynamicSharedMemorySize, 56320);

    k_init<<<193, 128>>>();
    k_dft<<<dim3(8, 256), 160>>>(x);
    k_xl2cy<<<dim3(45, 16), 512>>>(kern);
    k_zl <<<dim3(32, 16), 512, 108800>>>();
    k_ho <<<dim3(512, 5), 320, 56320>>>(bias, out);
}